// round 8
// baseline (speedup 1.0000x reference)
#include <cuda_runtime.h>
#include <cuda_bf16.h>

// ---------------- problem constants ----------------
#define NC 96          // B*C = 32*3
#define S0 510
#define S1 258         // (510+7)/2
#define S2 132         // (258+7)/2

// ---------------- static scratch ----------------
// Packed band planes: .x=a, .y=h, .z=v, .w=d
__device__ float  g_a1[NC * S1 * S1];    // dense a1 (input to level-2 analysis)
__device__ float4 g_p1[NC * S1 * S1];    // level-1 bands; .x rewritten with a1r by idwt2
__device__ float4 g_p2[NC * S2 * S2];    // level-2 bands
__device__ float  g_max[6 * NC];         // bands: 0..2 = h1,v1,d1 ; 3..5 = h2,v2,d2

// db4 filters (verified round 1)
__constant__ float CLO[8] = {
     0.23037781330885523f,  0.7148465705525415f,   0.6308807679295904f,
    -0.02798376941698385f, -0.18703481171888114f,  0.030841381835986965f,
     0.032883011666982945f,-0.010597401784997278f };
__constant__ float CHI[8] = {
    -0.010597401784997278f,-0.032883011666982945f, 0.030841381835986965f,
     0.18703481171888114f, -0.02798376941698385f, -0.6308807679295904f,
     0.7148465705525415f,  -0.23037781330885523f };

__device__ __forceinline__ int reflect(int idx, int S) {
    if (idx < 0)  return -1 - idx;
    if (idx >= S) return 2 * S - 1 - idx;
    return idx;
}

__device__ __forceinline__ float soft(float x, float t) {
    return copysignf(fmaxf(fabsf(x) * 1.5f - t, 0.f), x);
}

__global__ void init_max() {
    int i = blockIdx.x * blockDim.x + threadIdx.x;
    if (i < 6 * NC) g_max[i] = 0.f;
}

// ================= analysis: full-width strip, column DWT in registers =====
// Band mapping (fixed round 5): h-band <- rowLO(colHI)=vv ; v-band <- rowHI(colLO)=vh.
template<int H, int W, int Hc, int Wc, int BB, int BLK, bool WRITE_A>
__global__ void __launch_bounds__(BLK) dwt2_strip(
        const float* __restrict__ x,
        float* __restrict__ aplane, float4* __restrict__ packed) {
    constexpr int TKH = 8;
    constexpr int RN  = 2 * TKH + 6;   // 22 input rows per strip
    constexpr int WPAD = W + 12;       // 6 halo each side
    constexpr int NW  = BLK / 32;
    constexpr int WPR = (NW >= TKH) ? NW / TKH : 1;   // warps per coeff row
    __shared__ __align__(16) float sclo[TKH][WPAD];
    __shared__ __align__(16) float schi[TKH][WPAD];

    const int kh0 = blockIdx.x * TKH;
    const int nc  = blockIdx.y;
    const int tid = threadIdx.x;
    const float* xp = x + (size_t)nc * H * W;

    // Phase A: column DWT, one input column per thread (single pass: BLK >= W).
    for (int c = tid; c < W; c += BLK) {
        float xv[RN];
        const int r0 = 2 * kh0 - 6;
#pragma unroll
        for (int rr = 0; rr < RN; rr++) {
            int r = reflect(r0 + rr, H);
            xv[rr] = xp[(size_t)r * W + c];
        }
#pragma unroll
        for (int khl = 0; khl < TKH; khl++) {
            float al = 0.f, ah = 0.f;
#pragma unroll
            for (int t = 0; t < 8; t++) {
                float v = xv[2 * khl + t];
                al = fmaf(v, CLO[t], al);
                ah = fmaf(v, CHI[t], ah);
            }
            sclo[khl][6 + c] = al;
            schi[khl][6 + c] = ah;
        }
    }
    __syncthreads();

    // Halo fill: horizontal reflection commutes with the column transform.
    if (tid < 12 * TKH) {
        int hc = tid % 12, khl = tid / 12;
        int c   = (hc < 6) ? hc - 6 : W + (hc - 6);
        int src = (c < 0) ? -1 - c : 2 * W - 1 - c;
        sclo[khl][6 + c] = sclo[khl][6 + src];
        schi[khl][6 + c] = schi[khl][6 + src];
    }
    __syncthreads();

    // Phase B: row DWT; 2 coefficients per thread, vector stores.
    const int wid = tid >> 5, lane = tid & 31;
    const int row = wid / WPR, sub = wid % WPR;
    float m_h = 0.f, m_v = 0.f, m_d = 0.f;
    if (row < TKH) {
        const int kh = kh0 + row;
        if (kh < Hc) {
            const float2* plo = (const float2*)(&sclo[row][0]);
            const float2* phi = (const float2*)(&schi[row][0]);
            const unsigned ob = ((unsigned)nc * Hc + kh) * Wc;
            for (int k2 = lane + 32 * sub; k2 < Wc / 2; k2 += 32 * WPR) {
                const int k = 2 * k2;
                // plo[k+i] = sclo[row][2k+2i .. 2k+2i+1]; output k uses floats 2k..2k+7
                float2 l0 = plo[k],     l1 = plo[k + 1], l2 = plo[k + 2];
                float2 l3 = plo[k + 3], l4 = plo[k + 4];
                float2 h0 = phi[k],     h1 = phi[k + 1], h2 = phi[k + 2];
                float2 h3 = phi[k + 3], h4 = phi[k + 4];
                float va0, vh0, vv0, vd0, va1, vh1, vv1, vd1;
                va0 = fmaf(l0.x, CLO[0], fmaf(l0.y, CLO[1], fmaf(l1.x, CLO[2], fmaf(l1.y, CLO[3],
                      fmaf(l2.x, CLO[4], fmaf(l2.y, CLO[5], fmaf(l3.x, CLO[6], l3.y * CLO[7])))))));
                vh0 = fmaf(l0.x, CHI[0], fmaf(l0.y, CHI[1], fmaf(l1.x, CHI[2], fmaf(l1.y, CHI[3],
                      fmaf(l2.x, CHI[4], fmaf(l2.y, CHI[5], fmaf(l3.x, CHI[6], l3.y * CHI[7])))))));
                vv0 = fmaf(h0.x, CLO[0], fmaf(h0.y, CLO[1], fmaf(h1.x, CLO[2], fmaf(h1.y, CLO[3],
                      fmaf(h2.x, CLO[4], fmaf(h2.y, CLO[5], fmaf(h3.x, CLO[6], h3.y * CLO[7])))))));
                vd0 = fmaf(h0.x, CHI[0], fmaf(h0.y, CHI[1], fmaf(h1.x, CHI[2], fmaf(h1.y, CHI[3],
                      fmaf(h2.x, CHI[4], fmaf(h2.y, CHI[5], fmaf(h3.x, CHI[6], h3.y * CHI[7])))))));
                va1 = fmaf(l1.x, CLO[0], fmaf(l1.y, CLO[1], fmaf(l2.x, CLO[2], fmaf(l2.y, CLO[3],
                      fmaf(l3.x, CLO[4], fmaf(l3.y, CLO[5], fmaf(l4.x, CLO[6], l4.y * CLO[7])))))));
                vh1 = fmaf(l1.x, CHI[0], fmaf(l1.y, CHI[1], fmaf(l2.x, CHI[2], fmaf(l2.y, CHI[3],
                      fmaf(l3.x, CHI[4], fmaf(l3.y, CHI[5], fmaf(l4.x, CHI[6], l4.y * CHI[7])))))));
                vv1 = fmaf(h1.x, CLO[0], fmaf(h1.y, CLO[1], fmaf(h2.x, CLO[2], fmaf(h2.y, CLO[3],
                      fmaf(h3.x, CLO[4], fmaf(h3.y, CLO[5], fmaf(h4.x, CLO[6], h4.y * CLO[7])))))));
                vd1 = fmaf(h1.x, CHI[0], fmaf(h1.y, CHI[1], fmaf(h2.x, CHI[2], fmaf(h2.y, CHI[3],
                      fmaf(h3.x, CHI[4], fmaf(h3.y, CHI[5], fmaf(h4.x, CHI[6], h4.y * CHI[7])))))));
                if constexpr (WRITE_A)
                    *(float2*)&aplane[ob + k] = make_float2(va0, va1);
                packed[ob + k]     = make_float4(va0, vv0, vh0, vd0);
                packed[ob + k + 1] = make_float4(va1, vv1, vh1, vd1);
                m_h = fmaxf(m_h, fmaxf(fabsf(vv0), fabsf(vv1)));
                m_v = fmaxf(m_v, fmaxf(fabsf(vh0), fabsf(vh1)));
                m_d = fmaxf(m_d, fmaxf(fabsf(vd0), fabsf(vd1)));
            }
        }
    }

#pragma unroll
    for (int o = 16; o > 0; o >>= 1) {
        m_h = fmaxf(m_h, __shfl_xor_sync(0xffffffffu, m_h, o));
        m_v = fmaxf(m_v, __shfl_xor_sync(0xffffffffu, m_v, o));
        m_d = fmaxf(m_d, __shfl_xor_sync(0xffffffffu, m_d, o));
    }
    __shared__ float rmax[NW][3];
    if (lane == 0) { rmax[wid][0] = m_h; rmax[wid][1] = m_v; rmax[wid][2] = m_d; }
    __syncthreads();
    if (tid < 3) {
        float m = rmax[0][tid];
#pragma unroll
        for (int i = 1; i < NW; i++) m = fmaxf(m, rmax[i][tid]);
        atomicMax((int*)&g_max[(BB + tid) * NC + nc], __float_as_int(m));
    }
}

// ================= synthesis: full-width strip, split column IDWT ==========
// Phase A: thread = (column, half); 7 LDG.128 window per half, soft fused.
// Phase B: 2 output pairs per thread; dense float2 stores (idwt1) or
//          scalar .x component stores into the packed plane (idwt2 -> a1r).
template<int Hc, int Wc, int H, int W, int BB, int BLK, bool PACKOUT>
__global__ void __launch_bounds__(BLK) idwt2_strip(
        const float4* __restrict__ P,
        float* __restrict__ outd, float4* __restrict__ outp) {
    constexpr int TM  = 16;            // output rows per strip
    constexpr int PR  = 4;             // p-values per half
    constexpr int RWH = PR + 3;        // 7 coefficient rows per half
    constexpr int NW  = BLK / 32;
    __shared__ __align__(16) float slo[TM][Wc];
    __shared__ __align__(16) float shi[TM][Wc];

    const int m0  = blockIdx.x * TM;
    const int nc  = blockIdx.y;
    const int tid = threadIdx.x;
    const float th = 0.3f * g_max[(BB + 0) * NC + nc];
    const float tv = 0.3f * g_max[(BB + 1) * NC + nc];
    const float td = 0.3f * g_max[(BB + 2) * NC + nc];
    const int q0b = m0 >> 1;

    // Phase A: 2*Wc active threads, one LDG.128 batch per thread.
    if (tid < 2 * Wc) {
        const int wc = (tid < Wc) ? tid : tid - Wc;
        const int hf = (tid < Wc) ? 0 : 1;
        const int pb = hf * PR;                 // p base: 0 or 4
        const int qs = q0b + pb;
        const float4* Pp = P + (unsigned)nc * Hc * Wc;

        float4 Cw[RWH];
#pragma unroll
        for (int i = 0; i < RWH; i++) {
            int q = min(qs + i, Hc - 1);        // clamped rows feed only masked outputs
            Cw[i] = Pp[(unsigned)q * Wc + wc];
        }
        float Aw[RWH], Hw[RWH], Vw[RWH], Dw[RWH];
#pragma unroll
        for (int i = 0; i < RWH; i++) {
            Aw[i] = Cw[i].x;
            Hw[i] = soft(Cw[i].y, th);
            Vw[i] = soft(Cw[i].z, tv);
            Dw[i] = soft(Cw[i].w, td);
        }
#pragma unroll
        for (int pp = 0; pp < PR; pp++) {
            const int ml = 2 * (pb + pp);       // strip-local even output row
            float e_lo = 0.f, o_lo = 0.f, e_hi = 0.f, o_hi = 0.f;
#pragma unroll
            for (int i = 0; i < 4; i++) {
                e_lo = fmaf(Aw[pp + i], CLO[6 - 2 * i], fmaf(Hw[pp + i], CHI[6 - 2 * i], e_lo));
                o_lo = fmaf(Aw[pp + i], CLO[7 - 2 * i], fmaf(Hw[pp + i], CHI[7 - 2 * i], o_lo));
                e_hi = fmaf(Vw[pp + i], CLO[6 - 2 * i], fmaf(Dw[pp + i], CHI[6 - 2 * i], e_hi));
                o_hi = fmaf(Vw[pp + i], CLO[7 - 2 * i], fmaf(Dw[pp + i], CHI[7 - 2 * i], o_hi));
            }
            slo[ml][wc]     = e_lo;
            slo[ml + 1][wc] = o_lo;
            shi[ml][wc]     = e_hi;
            shi[ml + 1][wc] = o_hi;
        }
    }
    __syncthreads();

    // Phase B: row IDWT; 2 output pairs (4 pixels) per thread.
    const int wid = tid >> 5, lane = tid & 31;
    constexpr int NP  = W / 2;         // output pairs per row (may be odd)
    constexpr int NPP = (NP + 1) / 2;
    for (int rr = wid; rr < TM; rr += NW) {
        int m = m0 + rr;
        if (m >= H) break;
        float*  od = PACKOUT ? nullptr : (outd + (size_t)nc * H * W + (size_t)m * W);
        float4* op = PACKOUT ? (outp + (unsigned)nc * H * W + (unsigned)m * W) : nullptr;
        for (int wp2 = lane; wp2 < NPP; wp2 += 32) {
            const int wp = 2 * wp2;
            float2 l01 = *(const float2*)&slo[rr][wp];
            float2 l23 = *(const float2*)&slo[rr][wp + 2];
            float2 h01 = *(const float2*)&shi[rr][wp];
            float2 h23 = *(const float2*)&shi[rr][wp + 2];
            // pair 0: outputs 2wp, 2wp+1 from window [wp..wp+3]
            float ae0 = fmaf(l01.x, CLO[6], fmaf(l01.y, CLO[4], fmaf(l23.x, CLO[2], fmaf(l23.y, CLO[0],
                        fmaf(h01.x, CHI[6], fmaf(h01.y, CHI[4], fmaf(h23.x, CHI[2], h23.y * CHI[0])))))));
            float ao0 = fmaf(l01.x, CLO[7], fmaf(l01.y, CLO[5], fmaf(l23.x, CLO[3], fmaf(l23.y, CLO[1],
                        fmaf(h01.x, CHI[7], fmaf(h01.y, CHI[5], fmaf(h23.x, CHI[3], h23.y * CHI[1])))))));
            if constexpr (PACKOUT) {
                op[2 * wp].x     = ae0;
                op[2 * wp + 1].x = ao0;
            } else {
                *(float2*)&od[2 * wp] = make_float2(ae0, ao0);
            }
            if (wp + 1 < NP) {
                float l4 = (wp + 4 < Wc) ? slo[rr][wp + 4] : 0.f;
                float h4 = (wp + 4 < Wc) ? shi[rr][wp + 4] : 0.f;
                // pair 1: outputs 2wp+2, 2wp+3 from window [wp+1..wp+4]
                float ae1 = fmaf(l01.y, CLO[6], fmaf(l23.x, CLO[4], fmaf(l23.y, CLO[2], fmaf(l4, CLO[0],
                            fmaf(h01.y, CHI[6], fmaf(h23.x, CHI[4], fmaf(h23.y, CHI[2], h4 * CHI[0])))))));
                float ao1 = fmaf(l01.y, CLO[7], fmaf(l23.x, CLO[5], fmaf(l23.y, CLO[3], fmaf(l4, CLO[1],
                            fmaf(h01.y, CHI[7], fmaf(h23.x, CHI[5], fmaf(h23.y, CHI[3], h4 * CHI[1])))))));
                if constexpr (PACKOUT) {
                    op[2 * wp + 2].x = ae1;
                    op[2 * wp + 3].x = ao1;
                } else {
                    *(float2*)&od[2 * wp + 2] = make_float2(ae1, ao1);
                }
            }
        }
    }
}

// ---------------- host ----------------
static inline unsigned cdiv(unsigned a, unsigned b) { return (a + b - 1) / b; }

extern "C" void kernel_launch(void* const* d_in, const int* in_sizes, int n_in,
                              void* d_out, int out_size) {
    (void)in_sizes; (void)n_in; (void)out_size;
    const float* x = (const float*)d_in[0];
    float* out = (float*)d_out;

    float  *a1;
    float4 *p1, *p2;
    cudaGetSymbolAddress((void**)&a1, g_a1);
    cudaGetSymbolAddress((void**)&p1, g_p1);
    cudaGetSymbolAddress((void**)&p2, g_p2);

    init_max<<<3, 256>>>();

    // Level-1 analysis: x -> a1 (dense) + p1 (a,h,v,d packed) + absmax bands 0..2
    dwt2_strip<S0, S0, S1, S1, 0, 512, true><<<dim3(cdiv(S1, 8), NC), 512>>>(x, a1, p1);

    // Level-2 analysis: a1 -> p2 (a2,h2,v2,d2 packed) + absmax bands 3..5
    dwt2_strip<S1, S1, S2, S2, 3, 288, false><<<dim3(cdiv(S2, 8), NC), 288>>>(a1, nullptr, p2);

    // Level-2 synthesis: p2 -> a1r written into p1.x (refreshes the a-slot)
    idwt2_strip<S2, S2, S1, S1, 3, 288, true><<<dim3(cdiv(S1, 16), NC), 288>>>(p2, nullptr, p1);

    // Level-1 synthesis: p1 (a1r,h1,v1,d1) -> out
    idwt2_strip<S1, S1, S0, S0, 0, 544, false><<<dim3(cdiv(S0, 16), NC), 544>>>(p1, out, nullptr);
}

// round 9
// speedup vs baseline: 1.6937x; 1.6937x over previous
#include <cuda_runtime.h>
#include <cuda_bf16.h>

// ---------------- problem constants ----------------
#define NC 96          // B*C = 32*3
#define S0 510
#define S1 258         // (510+7)/2
#define S2 132         // (258+7)/2

// ---------------- static scratch ----------------
__device__ float  g_a1  [NC * S1 * S1];  // dense a1   (dwt1 out -> dwt2 in)
__device__ float  g_a1r [NC * S1 * S1];  // dense a1r  (idwt2 out -> idwt1 in)
__device__ float4 g_hvd1[NC * S1 * S1];  // level-1 details packed (x=h, y=v, z=d)
__device__ float4 g_p2  [NC * S2 * S2];  // level-2 packed (x=a, y=h, z=v, w=d)
__device__ float  g_max [6 * NC];        // bands: 0..2 = h1,v1,d1 ; 3..5 = h2,v2,d2

// db4 filters (verified round 1)
__constant__ float CLO[8] = {
     0.23037781330885523f,  0.7148465705525415f,   0.6308807679295904f,
    -0.02798376941698385f, -0.18703481171888114f,  0.030841381835986965f,
     0.032883011666982945f,-0.010597401784997278f };
__constant__ float CHI[8] = {
    -0.010597401784997278f,-0.032883011666982945f, 0.030841381835986965f,
     0.18703481171888114f, -0.02798376941698385f, -0.6308807679295904f,
     0.7148465705525415f,  -0.23037781330885523f };

__device__ __forceinline__ int reflect(int idx, int S) {
    if (idx < 0)  return -1 - idx;
    if (idx >= S) return 2 * S - 1 - idx;
    return idx;
}

__device__ __forceinline__ float soft(float x, float t) {
    return copysignf(fmaxf(fabsf(x) * 1.5f - t, 0.f), x);
}

__global__ void init_max() {
    int i = blockIdx.x * blockDim.x + threadIdx.x;
    if (i < 6 * NC) g_max[i] = 0.f;
}

// ================= analysis: full-width strip, column DWT in registers =====
// Band mapping (fixed round 5): h-band <- rowLO(colHI)=vv ; v-band <- rowHI(colLO)=vh.
// LEVEL1: aplane gets dense a (float2 stores); packed = (h,v,d,0).
// !LEVEL1: packed = (a,h,v,d); aplane unused.
template<int H, int W, int Hc, int Wc, int BB, int BLK, bool LEVEL1>
__global__ void __launch_bounds__(BLK) dwt2_strip(
        const float* __restrict__ x,
        float* __restrict__ aplane, float4* __restrict__ packed) {
    constexpr int TKH = 8;
    constexpr int RN  = 2 * TKH + 6;   // 22 input rows per strip
    constexpr int WPAD = W + 12;       // 6 halo each side (even)
    constexpr int NW  = BLK / 32;
    constexpr int WPR = (NW >= TKH) ? NW / TKH : 1;   // warps per coeff row
    __shared__ __align__(16) float sclo[TKH][WPAD];
    __shared__ __align__(16) float schi[TKH][WPAD];

    const int kh0 = blockIdx.x * TKH;
    const int nc  = blockIdx.y;
    const int tid = threadIdx.x;
    const float* xp = x + (size_t)nc * H * W;

    // Phase A: column DWT, one input column per thread (single pass: BLK >= W).
    for (int c = tid; c < W; c += BLK) {
        float xv[RN];
        const int r0 = 2 * kh0 - 6;
#pragma unroll
        for (int rr = 0; rr < RN; rr++) {
            int r = reflect(r0 + rr, H);
            xv[rr] = xp[(size_t)r * W + c];
        }
#pragma unroll
        for (int khl = 0; khl < TKH; khl++) {
            float al = 0.f, ah = 0.f;
#pragma unroll
            for (int t = 0; t < 8; t++) {
                float v = xv[2 * khl + t];
                al = fmaf(v, CLO[t], al);
                ah = fmaf(v, CHI[t], ah);
            }
            sclo[khl][6 + c] = al;
            schi[khl][6 + c] = ah;
        }
    }
    __syncthreads();

    // Halo fill: horizontal reflection commutes with the column transform.
    if (tid < 12 * TKH) {
        int hc = tid % 12, khl = tid / 12;
        int c   = (hc < 6) ? hc - 6 : W + (hc - 6);
        int src = (c < 0) ? -1 - c : 2 * W - 1 - c;
        sclo[khl][6 + c] = sclo[khl][6 + src];
        schi[khl][6 + c] = schi[khl][6 + src];
    }
    __syncthreads();

    // Phase B: row DWT; 2 coefficients per thread, full-width vector stores.
    const int wid = tid >> 5, lane = tid & 31;
    const int row = wid / WPR, sub = wid % WPR;
    float m_h = 0.f, m_v = 0.f, m_d = 0.f;
    if (row < TKH) {
        const int kh = kh0 + row;
        if (kh < Hc) {
            const float2* plo = (const float2*)(&sclo[row][0]);
            const float2* phi = (const float2*)(&schi[row][0]);
            const unsigned ob = ((unsigned)nc * Hc + kh) * Wc;
            for (int k2 = lane + 32 * sub; k2 < Wc / 2; k2 += 32 * WPR) {
                const int k = 2 * k2;
                float2 l0 = plo[k],     l1 = plo[k + 1], l2 = plo[k + 2];
                float2 l3 = plo[k + 3], l4 = plo[k + 4];
                float2 h0 = phi[k],     h1 = phi[k + 1], h2 = phi[k + 2];
                float2 h3 = phi[k + 3], h4 = phi[k + 4];
                float va0, vh0, vv0, vd0, va1, vh1, vv1, vd1;
                va0 = fmaf(l0.x, CLO[0], fmaf(l0.y, CLO[1], fmaf(l1.x, CLO[2], fmaf(l1.y, CLO[3],
                      fmaf(l2.x, CLO[4], fmaf(l2.y, CLO[5], fmaf(l3.x, CLO[6], l3.y * CLO[7])))))));
                vh0 = fmaf(l0.x, CHI[0], fmaf(l0.y, CHI[1], fmaf(l1.x, CHI[2], fmaf(l1.y, CHI[3],
                      fmaf(l2.x, CHI[4], fmaf(l2.y, CHI[5], fmaf(l3.x, CHI[6], l3.y * CHI[7])))))));
                vv0 = fmaf(h0.x, CLO[0], fmaf(h0.y, CLO[1], fmaf(h1.x, CLO[2], fmaf(h1.y, CLO[3],
                      fmaf(h2.x, CLO[4], fmaf(h2.y, CLO[5], fmaf(h3.x, CLO[6], h3.y * CLO[7])))))));
                vd0 = fmaf(h0.x, CHI[0], fmaf(h0.y, CHI[1], fmaf(h1.x, CHI[2], fmaf(h1.y, CHI[3],
                      fmaf(h2.x, CHI[4], fmaf(h2.y, CHI[5], fmaf(h3.x, CHI[6], h3.y * CHI[7])))))));
                va1 = fmaf(l1.x, CLO[0], fmaf(l1.y, CLO[1], fmaf(l2.x, CLO[2], fmaf(l2.y, CLO[3],
                      fmaf(l3.x, CLO[4], fmaf(l3.y, CLO[5], fmaf(l4.x, CLO[6], l4.y * CLO[7])))))));
                vh1 = fmaf(l1.x, CHI[0], fmaf(l1.y, CHI[1], fmaf(l2.x, CHI[2], fmaf(l2.y, CHI[3],
                      fmaf(l3.x, CHI[4], fmaf(l3.y, CHI[5], fmaf(l4.x, CHI[6], l4.y * CHI[7])))))));
                vv1 = fmaf(h1.x, CLO[0], fmaf(h1.y, CLO[1], fmaf(h2.x, CLO[2], fmaf(h2.y, CLO[3],
                      fmaf(h3.x, CLO[4], fmaf(h3.y, CLO[5], fmaf(h4.x, CLO[6], h4.y * CLO[7])))))));
                vd1 = fmaf(h1.x, CHI[0], fmaf(h1.y, CHI[1], fmaf(h2.x, CHI[2], fmaf(h2.y, CHI[3],
                      fmaf(h3.x, CHI[4], fmaf(h3.y, CHI[5], fmaf(h4.x, CHI[6], h4.y * CHI[7])))))));
                if constexpr (LEVEL1) {
                    *(float2*)&aplane[ob + k] = make_float2(va0, va1);
                    packed[ob + k]     = make_float4(vv0, vh0, vd0, 0.f);  // (h,v,d,·)
                    packed[ob + k + 1] = make_float4(vv1, vh1, vd1, 0.f);
                } else {
                    packed[ob + k]     = make_float4(va0, vv0, vh0, vd0);  // (a,h,v,d)
                    packed[ob + k + 1] = make_float4(va1, vv1, vh1, vd1);
                }
                m_h = fmaxf(m_h, fmaxf(fabsf(vv0), fabsf(vv1)));
                m_v = fmaxf(m_v, fmaxf(fabsf(vh0), fabsf(vh1)));
                m_d = fmaxf(m_d, fmaxf(fabsf(vd0), fabsf(vd1)));
            }
        }
    }

#pragma unroll
    for (int o = 16; o > 0; o >>= 1) {
        m_h = fmaxf(m_h, __shfl_xor_sync(0xffffffffu, m_h, o));
        m_v = fmaxf(m_v, __shfl_xor_sync(0xffffffffu, m_v, o));
        m_d = fmaxf(m_d, __shfl_xor_sync(0xffffffffu, m_d, o));
    }
    __shared__ float rmax[NW][3];
    if (lane == 0) { rmax[wid][0] = m_h; rmax[wid][1] = m_v; rmax[wid][2] = m_d; }
    __syncthreads();
    if (tid < 3) {
        float m = rmax[0][tid];
#pragma unroll
        for (int i = 1; i < NW; i++) m = fmaxf(m, rmax[i][tid]);
        atomicMax((int*)&g_max[(BB + tid) * NC + nc], __float_as_int(m));
    }
}

// ================= synthesis: full-width strip, split column IDWT ==========
// PA=true : P = (a,h,v,d) packed (level-2); Adense unused.
// PA=false: P = (h,v,d,·) packed; A read from dense Adense (level-1).
// All outputs dense float2 stores (the round-8 scattered-component store is banned).
template<int Hc, int Wc, int H, int W, int BB, int BLK, bool PA>
__global__ void __launch_bounds__(BLK) idwt2_strip(
        const float4* __restrict__ P, const float* __restrict__ Adense,
        float* __restrict__ outd) {
    constexpr int TM  = 16;            // output rows per strip
    constexpr int PR  = 4;             // p-values per half
    constexpr int RWH = PR + 3;        // 7 coefficient rows per half
    constexpr int NW  = BLK / 32;
    __shared__ __align__(16) float slo[TM][Wc];
    __shared__ __align__(16) float shi[TM][Wc];

    const int m0  = blockIdx.x * TM;
    const int nc  = blockIdx.y;
    const int tid = threadIdx.x;
    const float th = 0.3f * g_max[(BB + 0) * NC + nc];
    const float tv = 0.3f * g_max[(BB + 1) * NC + nc];
    const float td = 0.3f * g_max[(BB + 2) * NC + nc];
    const int q0b = m0 >> 1;

    // Phase A: 2*Wc active threads; one independent LDG.128 batch per thread.
    if (tid < 2 * Wc) {
        const int wc = (tid < Wc) ? tid : tid - Wc;
        const int hf = (tid < Wc) ? 0 : 1;
        const int pb = hf * PR;                 // p base: 0 or 4
        const int qs = q0b + pb;
        const float4* Pp = P + (unsigned)nc * Hc * Wc;

        float4 Cw[RWH];
        float  Aw[RWH];
#pragma unroll
        for (int i = 0; i < RWH; i++) {
            int q = min(qs + i, Hc - 1);        // clamped rows feed only masked outputs
            unsigned o = (unsigned)q * Wc + wc;
            Cw[i] = Pp[o];
            if constexpr (!PA) Aw[i] = Adense[(size_t)nc * Hc * Wc + o];
        }
        float Hw[RWH], Vw[RWH], Dw[RWH];
#pragma unroll
        for (int i = 0; i < RWH; i++) {
            if constexpr (PA) {
                Aw[i] = Cw[i].x;
                Hw[i] = soft(Cw[i].y, th);
                Vw[i] = soft(Cw[i].z, tv);
                Dw[i] = soft(Cw[i].w, td);
            } else {
                Hw[i] = soft(Cw[i].x, th);
                Vw[i] = soft(Cw[i].y, tv);
                Dw[i] = soft(Cw[i].z, td);
            }
        }
#pragma unroll
        for (int pp = 0; pp < PR; pp++) {
            const int ml = 2 * (pb + pp);       // strip-local even output row
            float e_lo = 0.f, o_lo = 0.f, e_hi = 0.f, o_hi = 0.f;
#pragma unroll
            for (int i = 0; i < 4; i++) {
                e_lo = fmaf(Aw[pp + i], CLO[6 - 2 * i], fmaf(Hw[pp + i], CHI[6 - 2 * i], e_lo));
                o_lo = fmaf(Aw[pp + i], CLO[7 - 2 * i], fmaf(Hw[pp + i], CHI[7 - 2 * i], o_lo));
                e_hi = fmaf(Vw[pp + i], CLO[6 - 2 * i], fmaf(Dw[pp + i], CHI[6 - 2 * i], e_hi));
                o_hi = fmaf(Vw[pp + i], CLO[7 - 2 * i], fmaf(Dw[pp + i], CHI[7 - 2 * i], o_hi));
            }
            slo[ml][wc]     = e_lo;
            slo[ml + 1][wc] = o_lo;
            shi[ml][wc]     = e_hi;
            shi[ml + 1][wc] = o_hi;
        }
    }
    __syncthreads();

    // Phase B: row IDWT; 2 output pairs (4 pixels) per thread, float2 stores.
    const int wid = tid >> 5, lane = tid & 31;
    constexpr int NP  = W / 2;         // output pairs per row (may be odd)
    constexpr int NPP = (NP + 1) / 2;
    for (int rr = wid; rr < TM; rr += NW) {
        int m = m0 + rr;
        if (m >= H) break;
        float* od = outd + (size_t)nc * H * W + (size_t)m * W;
        for (int wp2 = lane; wp2 < NPP; wp2 += 32) {
            const int wp = 2 * wp2;
            float2 l01 = *(const float2*)&slo[rr][wp];
            float2 l23 = *(const float2*)&slo[rr][wp + 2];
            float2 h01 = *(const float2*)&shi[rr][wp];
            float2 h23 = *(const float2*)&shi[rr][wp + 2];
            float ae0 = fmaf(l01.x, CLO[6], fmaf(l01.y, CLO[4], fmaf(l23.x, CLO[2], fmaf(l23.y, CLO[0],
                        fmaf(h01.x, CHI[6], fmaf(h01.y, CHI[4], fmaf(h23.x, CHI[2], h23.y * CHI[0])))))));
            float ao0 = fmaf(l01.x, CLO[7], fmaf(l01.y, CLO[5], fmaf(l23.x, CLO[3], fmaf(l23.y, CLO[1],
                        fmaf(h01.x, CHI[7], fmaf(h01.y, CHI[5], fmaf(h23.x, CHI[3], h23.y * CHI[1])))))));
            *(float2*)&od[2 * wp] = make_float2(ae0, ao0);
            if (wp + 1 < NP) {
                float l4 = (wp + 4 < Wc) ? slo[rr][wp + 4] : 0.f;
                float h4 = (wp + 4 < Wc) ? shi[rr][wp + 4] : 0.f;
                float ae1 = fmaf(l01.y, CLO[6], fmaf(l23.x, CLO[4], fmaf(l23.y, CLO[2], fmaf(l4, CLO[0],
                            fmaf(h01.y, CHI[6], fmaf(h23.x, CHI[4], fmaf(h23.y, CHI[2], h4 * CHI[0])))))));
                float ao1 = fmaf(l01.y, CLO[7], fmaf(l23.x, CLO[5], fmaf(l23.y, CLO[3], fmaf(l4, CLO[1],
                            fmaf(h01.y, CHI[7], fmaf(h23.x, CHI[5], fmaf(h23.y, CHI[3], h4 * CHI[1])))))));
                *(float2*)&od[2 * wp + 2] = make_float2(ae1, ao1);
            }
        }
    }
}

// ---------------- host ----------------
static inline unsigned cdiv(unsigned a, unsigned b) { return (a + b - 1) / b; }

extern "C" void kernel_launch(void* const* d_in, const int* in_sizes, int n_in,
                              void* d_out, int out_size) {
    (void)in_sizes; (void)n_in; (void)out_size;
    const float* x = (const float*)d_in[0];
    float* out = (float*)d_out;

    float  *a1, *a1r;
    float4 *hvd1, *p2;
    cudaGetSymbolAddress((void**)&a1,   g_a1);
    cudaGetSymbolAddress((void**)&a1r,  g_a1r);
    cudaGetSymbolAddress((void**)&hvd1, g_hvd1);
    cudaGetSymbolAddress((void**)&p2,   g_p2);

    init_max<<<3, 256>>>();

    // Level-1 analysis: x -> a1 (dense) + hvd1 packed + absmax bands 0..2
    dwt2_strip<S0, S0, S1, S1, 0, 512, true><<<dim3(cdiv(S1, 8), NC), 512>>>(x, a1, hvd1);

    // Level-2 analysis: a1 -> p2 (a,h,v,d) + absmax bands 3..5
    dwt2_strip<S1, S1, S2, S2, 3, 288, false><<<dim3(cdiv(S2, 8), NC), 288>>>(a1, nullptr, p2);

    // Level-2 synthesis: p2 -> a1r (dense float2 stores)
    idwt2_strip<S2, S2, S1, S1, 3, 288, true><<<dim3(cdiv(S1, 16), NC), 288>>>(p2, nullptr, a1r);

    // Level-1 synthesis: (a1r dense, hvd1 packed) -> out
    idwt2_strip<S1, S1, S0, S0, 0, 544, false><<<dim3(cdiv(S0, 16), NC), 544>>>(hvd1, a1r, out);
}

// round 10
// speedup vs baseline: 1.7955x; 1.0601x over previous
#include <cuda_runtime.h>
#include <cuda_bf16.h>

// ---------------- problem constants ----------------
#define NC 96          // B*C = 32*3
#define S0 510
#define S1 258         // (510+7)/2
#define S2 132         // (258+7)/2

// ---------------- static scratch ----------------
__device__ float  g_a1 [NC * S1 * S1];   // dense a1   (dwt1 out -> dwt2 in)
__device__ float  g_a1r[NC * S1 * S1];   // dense a1r  (idwt2 out -> idwt1 in)
__device__ float2 g_hv1[NC * S1 * S1];   // level-1 (h,v) packed
__device__ float  g_d1 [NC * S1 * S1];   // level-1 d plane
__device__ float4 g_p2 [NC * S2 * S2];   // level-2 packed (x=a, y=h, z=v, w=d)
__device__ float  g_max[6 * NC];         // bands: 0..2 = h1,v1,d1 ; 3..5 = h2,v2,d2

// db4 filters (verified round 1)
__constant__ float CLO[8] = {
     0.23037781330885523f,  0.7148465705525415f,   0.6308807679295904f,
    -0.02798376941698385f, -0.18703481171888114f,  0.030841381835986965f,
     0.032883011666982945f,-0.010597401784997278f };
__constant__ float CHI[8] = {
    -0.010597401784997278f,-0.032883011666982945f, 0.030841381835986965f,
     0.18703481171888114f, -0.02798376941698385f, -0.6308807679295904f,
     0.7148465705525415f,  -0.23037781330885523f };

__device__ __forceinline__ int reflect(int idx, int S) {
    if (idx < 0)  return -1 - idx;
    if (idx >= S) return 2 * S - 1 - idx;
    return idx;
}

__device__ __forceinline__ float soft(float x, float t) {
    return copysignf(fmaxf(fabsf(x) * 1.5f - t, 0.f), x);
}

__global__ void init_max() {
    int i = blockIdx.x * blockDim.x + threadIdx.x;
    if (i < 6 * NC) g_max[i] = 0.f;
}

// ================= analysis: full-width strip, column DWT in registers =====
// Band mapping (fixed round 5): h-band <- rowLO(colHI)=vv ; v-band <- rowHI(colLO)=vh.
// LEVEL1: aplane (dense), hvplane (float2 pairs), dplane (dense).
// !LEVEL1: packed = (a,h,v,d) float4.
template<int H, int W, int Hc, int Wc, int BB, int BLK, bool LEVEL1>
__global__ void __launch_bounds__(BLK) dwt2_strip(
        const float* __restrict__ x,
        float* __restrict__ aplane, float2* __restrict__ hvplane,
        float* __restrict__ dplane, float4* __restrict__ packed) {
    constexpr int TKH = 8;
    constexpr int RN  = 2 * TKH + 6;   // 22 input rows per strip
    constexpr int WPAD = W + 12;       // 6 halo each side (even)
    constexpr int NW  = BLK / 32;
    constexpr int WPR = (NW >= TKH) ? NW / TKH : 1;   // warps per coeff row
    __shared__ __align__(16) float sclo[TKH][WPAD];
    __shared__ __align__(16) float schi[TKH][WPAD];

    const int kh0 = blockIdx.x * TKH;
    const int nc  = blockIdx.y;
    const int tid = threadIdx.x;
    const float* xp = x + (size_t)nc * H * W;

    // Phase A: column DWT, one input column per thread (single pass: BLK >= W).
    for (int c = tid; c < W; c += BLK) {
        float xv[RN];
        const int r0 = 2 * kh0 - 6;
#pragma unroll
        for (int rr = 0; rr < RN; rr++) {
            int r = reflect(r0 + rr, H);
            xv[rr] = xp[(size_t)r * W + c];
        }
#pragma unroll
        for (int khl = 0; khl < TKH; khl++) {
            float al = 0.f, ah = 0.f;
#pragma unroll
            for (int t = 0; t < 8; t++) {
                float v = xv[2 * khl + t];
                al = fmaf(v, CLO[t], al);
                ah = fmaf(v, CHI[t], ah);
            }
            sclo[khl][6 + c] = al;
            schi[khl][6 + c] = ah;
        }
    }
    __syncthreads();

    // Halo fill: horizontal reflection commutes with the column transform.
    if (tid < 12 * TKH) {
        int hc = tid % 12, khl = tid / 12;
        int c   = (hc < 6) ? hc - 6 : W + (hc - 6);
        int src = (c < 0) ? -1 - c : 2 * W - 1 - c;
        sclo[khl][6 + c] = sclo[khl][6 + src];
        schi[khl][6 + c] = schi[khl][6 + src];
    }
    __syncthreads();

    // Phase B: row DWT; 2 coefficients per thread, vector stores, no padding.
    const int wid = tid >> 5, lane = tid & 31;
    const int row = wid / WPR, sub = wid % WPR;
    float m_h = 0.f, m_v = 0.f, m_d = 0.f;
    if (row < TKH) {
        const int kh = kh0 + row;
        if (kh < Hc) {
            const float2* plo = (const float2*)(&sclo[row][0]);
            const float2* phi = (const float2*)(&schi[row][0]);
            const unsigned ob = ((unsigned)nc * Hc + kh) * Wc;
            for (int k2 = lane + 32 * sub; k2 < Wc / 2; k2 += 32 * WPR) {
                const int k = 2 * k2;
                float2 l0 = plo[k],     l1 = plo[k + 1], l2 = plo[k + 2];
                float2 l3 = plo[k + 3], l4 = plo[k + 4];
                float2 h0 = phi[k],     h1 = phi[k + 1], h2 = phi[k + 2];
                float2 h3 = phi[k + 3], h4 = phi[k + 4];
                float va0, vh0, vv0, vd0, va1, vh1, vv1, vd1;
                va0 = fmaf(l0.x, CLO[0], fmaf(l0.y, CLO[1], fmaf(l1.x, CLO[2], fmaf(l1.y, CLO[3],
                      fmaf(l2.x, CLO[4], fmaf(l2.y, CLO[5], fmaf(l3.x, CLO[6], l3.y * CLO[7])))))));
                vh0 = fmaf(l0.x, CHI[0], fmaf(l0.y, CHI[1], fmaf(l1.x, CHI[2], fmaf(l1.y, CHI[3],
                      fmaf(l2.x, CHI[4], fmaf(l2.y, CHI[5], fmaf(l3.x, CHI[6], l3.y * CHI[7])))))));
                vv0 = fmaf(h0.x, CLO[0], fmaf(h0.y, CLO[1], fmaf(h1.x, CLO[2], fmaf(h1.y, CLO[3],
                      fmaf(h2.x, CLO[4], fmaf(h2.y, CLO[5], fmaf(h3.x, CLO[6], h3.y * CLO[7])))))));
                vd0 = fmaf(h0.x, CHI[0], fmaf(h0.y, CHI[1], fmaf(h1.x, CHI[2], fmaf(h1.y, CHI[3],
                      fmaf(h2.x, CHI[4], fmaf(h2.y, CHI[5], fmaf(h3.x, CHI[6], h3.y * CHI[7])))))));
                va1 = fmaf(l1.x, CLO[0], fmaf(l1.y, CLO[1], fmaf(l2.x, CLO[2], fmaf(l2.y, CLO[3],
                      fmaf(l3.x, CLO[4], fmaf(l3.y, CLO[5], fmaf(l4.x, CLO[6], l4.y * CLO[7])))))));
                vh1 = fmaf(l1.x, CHI[0], fmaf(l1.y, CHI[1], fmaf(l2.x, CHI[2], fmaf(l2.y, CHI[3],
                      fmaf(l3.x, CHI[4], fmaf(l3.y, CHI[5], fmaf(l4.x, CHI[6], l4.y * CHI[7])))))));
                vv1 = fmaf(h1.x, CLO[0], fmaf(h1.y, CLO[1], fmaf(h2.x, CLO[2], fmaf(h2.y, CLO[3],
                      fmaf(h3.x, CLO[4], fmaf(h3.y, CLO[5], fmaf(h4.x, CLO[6], h4.y * CLO[7])))))));
                vd1 = fmaf(h1.x, CHI[0], fmaf(h1.y, CHI[1], fmaf(h2.x, CHI[2], fmaf(h2.y, CHI[3],
                      fmaf(h3.x, CHI[4], fmaf(h3.y, CHI[5], fmaf(h4.x, CHI[6], h4.y * CHI[7])))))));
                if constexpr (LEVEL1) {
                    *(float2*)&aplane[ob + k]  = make_float2(va0, va1);
                    // (h,v) pairs for k and k+1 -> one 16B store (ob+k even)
                    *(float4*)&hvplane[ob + k] = make_float4(vv0, vh0, vv1, vh1);
                    *(float2*)&dplane[ob + k]  = make_float2(vd0, vd1);
                } else {
                    packed[ob + k]     = make_float4(va0, vv0, vh0, vd0);  // (a,h,v,d)
                    packed[ob + k + 1] = make_float4(va1, vv1, vh1, vd1);
                }
                m_h = fmaxf(m_h, fmaxf(fabsf(vv0), fabsf(vv1)));
                m_v = fmaxf(m_v, fmaxf(fabsf(vh0), fabsf(vh1)));
                m_d = fmaxf(m_d, fmaxf(fabsf(vd0), fabsf(vd1)));
            }
        }
    }

#pragma unroll
    for (int o = 16; o > 0; o >>= 1) {
        m_h = fmaxf(m_h, __shfl_xor_sync(0xffffffffu, m_h, o));
        m_v = fmaxf(m_v, __shfl_xor_sync(0xffffffffu, m_v, o));
        m_d = fmaxf(m_d, __shfl_xor_sync(0xffffffffu, m_d, o));
    }
    __shared__ float rmax[NW][3];
    if (lane == 0) { rmax[wid][0] = m_h; rmax[wid][1] = m_v; rmax[wid][2] = m_d; }
    __syncthreads();
    if (tid < 3) {
        float m = rmax[0][tid];
#pragma unroll
        for (int i = 1; i < NW; i++) m = fmaxf(m, rmax[i][tid]);
        atomicMax((int*)&g_max[(BB + tid) * NC + nc], __float_as_int(m));
    }
}

// ================= synthesis: full-width strip, split column IDWT ==========
// PA=true : level-2; bands from P4 = (a,h,v,d).
// PA=false: level-1; bands from HV (float2), D (dense), A (dense a1r).
// All outputs dense float2 stores.
template<int Hc, int Wc, int H, int W, int BB, int BLK, bool PA>
__global__ void __launch_bounds__(BLK) idwt2_strip(
        const float4* __restrict__ P4,  const float2* __restrict__ HV,
        const float* __restrict__ Dp,   const float* __restrict__ Ap,
        float* __restrict__ outd) {
    constexpr int TM  = 16;            // output rows per strip
    constexpr int PR  = 4;             // p-values per half
    constexpr int RWH = PR + 3;        // 7 coefficient rows per half
    constexpr int NW  = BLK / 32;
    __shared__ __align__(16) float slo[TM][Wc];
    __shared__ __align__(16) float shi[TM][Wc];

    const int m0  = blockIdx.x * TM;
    const int nc  = blockIdx.y;
    const int tid = threadIdx.x;
    const float th = 0.3f * g_max[(BB + 0) * NC + nc];
    const float tv = 0.3f * g_max[(BB + 1) * NC + nc];
    const float td = 0.3f * g_max[(BB + 2) * NC + nc];
    const int q0b = m0 >> 1;

    // Phase A: 2*Wc active threads; one independent vector-load batch per thread.
    if (tid < 2 * Wc) {
        const int wc = (tid < Wc) ? tid : tid - Wc;
        const int hf = (tid < Wc) ? 0 : 1;
        const int pb = hf * PR;                 // p base: 0 or 4
        const int qs = q0b + pb;
        const size_t cb = (size_t)nc * Hc * Wc;

        float Aw[RWH], Hw[RWH], Vw[RWH], Dw[RWH];
        if constexpr (PA) {
            float4 Cw[RWH];
#pragma unroll
            for (int i = 0; i < RWH; i++) {
                int q = min(qs + i, Hc - 1);    // clamped rows feed only masked outputs
                Cw[i] = P4[cb + (unsigned)q * Wc + wc];
            }
#pragma unroll
            for (int i = 0; i < RWH; i++) {
                Aw[i] = Cw[i].x;
                Hw[i] = soft(Cw[i].y, th);
                Vw[i] = soft(Cw[i].z, tv);
                Dw[i] = soft(Cw[i].w, td);
            }
        } else {
            float2 hv[RWH]; float dv[RWH], av[RWH];
#pragma unroll
            for (int i = 0; i < RWH; i++) {
                int q = min(qs + i, Hc - 1);
                size_t o = cb + (unsigned)q * Wc + wc;
                hv[i] = HV[o];
                dv[i] = Dp[o];
                av[i] = Ap[o];
            }
#pragma unroll
            for (int i = 0; i < RWH; i++) {
                Aw[i] = av[i];
                Hw[i] = soft(hv[i].x, th);
                Vw[i] = soft(hv[i].y, tv);
                Dw[i] = soft(dv[i], td);
            }
        }
#pragma unroll
        for (int pp = 0; pp < PR; pp++) {
            const int ml = 2 * (pb + pp);       // strip-local even output row
            float e_lo = 0.f, o_lo = 0.f, e_hi = 0.f, o_hi = 0.f;
#pragma unroll
            for (int i = 0; i < 4; i++) {
                e_lo = fmaf(Aw[pp + i], CLO[6 - 2 * i], fmaf(Hw[pp + i], CHI[6 - 2 * i], e_lo));
                o_lo = fmaf(Aw[pp + i], CLO[7 - 2 * i], fmaf(Hw[pp + i], CHI[7 - 2 * i], o_lo));
                e_hi = fmaf(Vw[pp + i], CLO[6 - 2 * i], fmaf(Dw[pp + i], CHI[6 - 2 * i], e_hi));
                o_hi = fmaf(Vw[pp + i], CLO[7 - 2 * i], fmaf(Dw[pp + i], CHI[7 - 2 * i], o_hi));
            }
            slo[ml][wc]     = e_lo;
            slo[ml + 1][wc] = o_lo;
            shi[ml][wc]     = e_hi;
            shi[ml + 1][wc] = o_hi;
        }
    }
    __syncthreads();

    // Phase B: row IDWT; 2 output pairs (4 pixels) per thread, float2 stores.
    const int wid = tid >> 5, lane = tid & 31;
    constexpr int NP  = W / 2;         // output pairs per row (may be odd)
    constexpr int NPP = (NP + 1) / 2;
    for (int rr = wid; rr < TM; rr += NW) {
        int m = m0 + rr;
        if (m >= H) break;
        float* od = outd + (size_t)nc * H * W + (size_t)m * W;
        for (int wp2 = lane; wp2 < NPP; wp2 += 32) {
            const int wp = 2 * wp2;
            float2 l01 = *(const float2*)&slo[rr][wp];
            float2 l23 = *(const float2*)&slo[rr][wp + 2];
            float2 h01 = *(const float2*)&shi[rr][wp];
            float2 h23 = *(const float2*)&shi[rr][wp + 2];
            float ae0 = fmaf(l01.x, CLO[6], fmaf(l01.y, CLO[4], fmaf(l23.x, CLO[2], fmaf(l23.y, CLO[0],
                        fmaf(h01.x, CHI[6], fmaf(h01.y, CHI[4], fmaf(h23.x, CHI[2], h23.y * CHI[0])))))));
            float ao0 = fmaf(l01.x, CLO[7], fmaf(l01.y, CLO[5], fmaf(l23.x, CLO[3], fmaf(l23.y, CLO[1],
                        fmaf(h01.x, CHI[7], fmaf(h01.y, CHI[5], fmaf(h23.x, CHI[3], h23.y * CHI[1])))))));
            *(float2*)&od[2 * wp] = make_float2(ae0, ao0);
            if (wp + 1 < NP) {
                float l4 = (wp + 4 < Wc) ? slo[rr][wp + 4] : 0.f;
                float h4 = (wp + 4 < Wc) ? shi[rr][wp + 4] : 0.f;
                float ae1 = fmaf(l01.y, CLO[6], fmaf(l23.x, CLO[4], fmaf(l23.y, CLO[2], fmaf(l4, CLO[0],
                            fmaf(h01.y, CHI[6], fmaf(h23.x, CHI[4], fmaf(h23.y, CHI[2], h4 * CHI[0])))))));
                float ao1 = fmaf(l01.y, CLO[7], fmaf(l23.x, CLO[5], fmaf(l23.y, CLO[3], fmaf(l4, CLO[1],
                            fmaf(h01.y, CHI[7], fmaf(h23.x, CHI[5], fmaf(h23.y, CHI[3], h4 * CHI[1])))))));
                *(float2*)&od[2 * wp + 2] = make_float2(ae1, ao1);
            }
        }
    }
}

// ---------------- host ----------------
static inline unsigned cdiv(unsigned a, unsigned b) { return (a + b - 1) / b; }

extern "C" void kernel_launch(void* const* d_in, const int* in_sizes, int n_in,
                              void* d_out, int out_size) {
    (void)in_sizes; (void)n_in; (void)out_size;
    const float* x = (const float*)d_in[0];
    float* out = (float*)d_out;

    float  *a1, *a1r, *d1;
    float2 *hv1;
    float4 *p2;
    cudaGetSymbolAddress((void**)&a1,  g_a1);
    cudaGetSymbolAddress((void**)&a1r, g_a1r);
    cudaGetSymbolAddress((void**)&d1,  g_d1);
    cudaGetSymbolAddress((void**)&hv1, g_hv1);
    cudaGetSymbolAddress((void**)&p2,  g_p2);

    init_max<<<3, 256>>>();

    // Level-1 analysis: x -> a1 + hv1 + d1 (+ absmax bands 0..2)
    dwt2_strip<S0, S0, S1, S1, 0, 512, true><<<dim3(cdiv(S1, 8), NC), 512>>>(
        x, a1, hv1, d1, nullptr);

    // Level-2 analysis: a1 -> p2 (a,h,v,d) (+ absmax bands 3..5)
    dwt2_strip<S1, S1, S2, S2, 3, 288, false><<<dim3(cdiv(S2, 8), NC), 288>>>(
        a1, nullptr, nullptr, nullptr, p2);

    // Level-2 synthesis: p2 -> a1r (dense)
    idwt2_strip<S2, S2, S1, S1, 3, 288, true><<<dim3(cdiv(S1, 16), NC), 288>>>(
        p2, nullptr, nullptr, nullptr, a1r);

    // Level-1 synthesis: (a1r, hv1, d1) -> out
    idwt2_strip<S1, S1, S0, S0, 0, 544, false><<<dim3(cdiv(S0, 16), NC), 544>>>(
        nullptr, hv1, d1, a1r, out);
}

// round 12
// speedup vs baseline: 1.8352x; 1.0221x over previous
#include <cuda_runtime.h>
#include <cuda_bf16.h>

// ---------------- problem constants ----------------
#define NC 96          // B*C = 32*3
#define S0 510
#define S1 258         // (510+7)/2
#define S2 132         // (258+7)/2

// ---------------- static scratch ----------------
__device__ float  g_a1 [NC * S1 * S1];   // dense a1   (dwt1 out -> dwt2 in)
__device__ float  g_a1r[NC * S1 * S1];   // dense a1r  (idwt2 out -> idwt1 in)
__device__ float2 g_hv1[NC * S1 * S1];   // level-1 (h,v) packed
__device__ float  g_d1 [NC * S1 * S1];   // level-1 d plane
__device__ float4 g_p2 [NC * S2 * S2];   // level-2 packed (x=a, y=h, z=v, w=d)
__device__ float  g_max[6 * NC];         // bands: 0..2 = h1,v1,d1 ; 3..5 = h2,v2,d2

// db4 filters (verified round 1)
__constant__ float CLO[8] = {
     0.23037781330885523f,  0.7148465705525415f,   0.6308807679295904f,
    -0.02798376941698385f, -0.18703481171888114f,  0.030841381835986965f,
     0.032883011666982945f,-0.010597401784997278f };
__constant__ float CHI[8] = {
    -0.010597401784997278f,-0.032883011666982945f, 0.030841381835986965f,
     0.18703481171888114f, -0.02798376941698385f, -0.6308807679295904f,
     0.7148465705525415f,  -0.23037781330885523f };

__device__ __forceinline__ int reflect(int idx, int S) {
    if (idx < 0)  return -1 - idx;
    if (idx >= S) return 2 * S - 1 - idx;
    return idx;
}

__device__ __forceinline__ float soft(float x, float t) {
    return copysignf(fmaxf(fabsf(x) * 1.5f - t, 0.f), x);
}

__global__ void init_max() {
    int i = threadIdx.x;
    if (i < 6 * NC) g_max[i] = 0.f;
}

// ================= analysis: full-width strip, column DWT in registers =====
// Band mapping (fixed round 5): h-band <- rowLO(colHI)=vv ; v-band <- rowHI(colLO)=vh.
template<int H, int W, int Hc, int Wc, int BB, int BLK, bool LEVEL1>
__global__ void __launch_bounds__(BLK) dwt2_strip(
        const float* __restrict__ x,
        float* __restrict__ aplane, float2* __restrict__ hvplane,
        float* __restrict__ dplane, float4* __restrict__ packed) {
    constexpr int TKH = 8;
    constexpr int RN  = 2 * TKH + 6;   // 22 input rows per strip
    constexpr int WPAD = W + 12;       // 6 halo each side (even)
    constexpr int NW  = BLK / 32;
    constexpr int WPR = (NW >= TKH) ? NW / TKH : 1;   // warps per coeff row
    __shared__ __align__(16) float sclo[TKH][WPAD];
    __shared__ __align__(16) float schi[TKH][WPAD];

    const int kh0 = blockIdx.x * TKH;
    const int nc  = blockIdx.y;
    const int tid = threadIdx.x;
    const float* xp = x + (size_t)nc * H * W;

    // Phase A: column DWT, one input column per thread (single pass: BLK >= W).
    for (int c = tid; c < W; c += BLK) {
        float xv[RN];
        const int r0 = 2 * kh0 - 6;
#pragma unroll
        for (int rr = 0; rr < RN; rr++) {
            int r = reflect(r0 + rr, H);
            xv[rr] = xp[(size_t)r * W + c];
        }
#pragma unroll
        for (int khl = 0; khl < TKH; khl++) {
            float al = 0.f, ah = 0.f;
#pragma unroll
            for (int t = 0; t < 8; t++) {
                float v = xv[2 * khl + t];
                al = fmaf(v, CLO[t], al);
                ah = fmaf(v, CHI[t], ah);
            }
            sclo[khl][6 + c] = al;
            schi[khl][6 + c] = ah;
        }
    }
    __syncthreads();

    // Halo fill: horizontal reflection commutes with the column transform.
    if (tid < 12 * TKH) {
        int hc = tid % 12, khl = tid / 12;
        int c   = (hc < 6) ? hc - 6 : W + (hc - 6);
        int src = (c < 0) ? -1 - c : 2 * W - 1 - c;
        sclo[khl][6 + c] = sclo[khl][6 + src];
        schi[khl][6 + c] = schi[khl][6 + src];
    }
    __syncthreads();

    // Phase B: row DWT; 2 coefficients per thread, vector stores, no padding.
    const int wid = tid >> 5, lane = tid & 31;
    const int row = wid / WPR, sub = wid % WPR;
    float m_h = 0.f, m_v = 0.f, m_d = 0.f;
    if (row < TKH) {
        const int kh = kh0 + row;
        if (kh < Hc) {
            const float2* plo = (const float2*)(&sclo[row][0]);
            const float2* phi = (const float2*)(&schi[row][0]);
            const unsigned ob = ((unsigned)nc * Hc + kh) * Wc;
            for (int k2 = lane + 32 * sub; k2 < Wc / 2; k2 += 32 * WPR) {
                const int k = 2 * k2;
                float2 l0 = plo[k],     l1 = plo[k + 1], l2 = plo[k + 2];
                float2 l3 = plo[k + 3], l4 = plo[k + 4];
                float2 h0 = phi[k],     h1 = phi[k + 1], h2 = phi[k + 2];
                float2 h3 = phi[k + 3], h4 = phi[k + 4];
                float va0, vh0, vv0, vd0, va1, vh1, vv1, vd1;
                va0 = fmaf(l0.x, CLO[0], fmaf(l0.y, CLO[1], fmaf(l1.x, CLO[2], fmaf(l1.y, CLO[3],
                      fmaf(l2.x, CLO[4], fmaf(l2.y, CLO[5], fmaf(l3.x, CLO[6], l3.y * CLO[7])))))));
                vh0 = fmaf(l0.x, CHI[0], fmaf(l0.y, CHI[1], fmaf(l1.x, CHI[2], fmaf(l1.y, CHI[3],
                      fmaf(l2.x, CHI[4], fmaf(l2.y, CHI[5], fmaf(l3.x, CHI[6], l3.y * CHI[7])))))));
                vv0 = fmaf(h0.x, CLO[0], fmaf(h0.y, CLO[1], fmaf(h1.x, CLO[2], fmaf(h1.y, CLO[3],
                      fmaf(h2.x, CLO[4], fmaf(h2.y, CLO[5], fmaf(h3.x, CLO[6], h3.y * CLO[7])))))));
                vd0 = fmaf(h0.x, CHI[0], fmaf(h0.y, CHI[1], fmaf(h1.x, CHI[2], fmaf(h1.y, CHI[3],
                      fmaf(h2.x, CHI[4], fmaf(h2.y, CHI[5], fmaf(h3.x, CHI[6], h3.y * CHI[7])))))));
                va1 = fmaf(l1.x, CLO[0], fmaf(l1.y, CLO[1], fmaf(l2.x, CLO[2], fmaf(l2.y, CLO[3],
                      fmaf(l3.x, CLO[4], fmaf(l3.y, CLO[5], fmaf(l4.x, CLO[6], l4.y * CLO[7])))))));
                vh1 = fmaf(l1.x, CHI[0], fmaf(l1.y, CHI[1], fmaf(l2.x, CHI[2], fmaf(l2.y, CHI[3],
                      fmaf(l3.x, CHI[4], fmaf(l3.y, CHI[5], fmaf(l4.x, CHI[6], l4.y * CHI[7])))))));
                vv1 = fmaf(h1.x, CLO[0], fmaf(h1.y, CLO[1], fmaf(h2.x, CLO[2], fmaf(h2.y, CLO[3],
                      fmaf(h3.x, CLO[4], fmaf(h3.y, CLO[5], fmaf(h4.x, CLO[6], h4.y * CLO[7])))))));
                vd1 = fmaf(h1.x, CHI[0], fmaf(h1.y, CHI[1], fmaf(h2.x, CHI[2], fmaf(h2.y, CHI[3],
                      fmaf(h3.x, CHI[4], fmaf(h3.y, CHI[5], fmaf(h4.x, CHI[6], h4.y * CHI[7])))))));
                if constexpr (LEVEL1) {
                    *(float2*)&aplane[ob + k]  = make_float2(va0, va1);
                    *(float4*)&hvplane[ob + k] = make_float4(vv0, vh0, vv1, vh1);
                    *(float2*)&dplane[ob + k]  = make_float2(vd0, vd1);
                } else {
                    packed[ob + k]     = make_float4(va0, vv0, vh0, vd0);
                    packed[ob + k + 1] = make_float4(va1, vv1, vh1, vd1);
                }
                m_h = fmaxf(m_h, fmaxf(fabsf(vv0), fabsf(vv1)));
                m_v = fmaxf(m_v, fmaxf(fabsf(vh0), fabsf(vh1)));
                m_d = fmaxf(m_d, fmaxf(fabsf(vd0), fabsf(vd1)));
            }
        }
    }

#pragma unroll
    for (int o = 16; o > 0; o >>= 1) {
        m_h = fmaxf(m_h, __shfl_xor_sync(0xffffffffu, m_h, o));
        m_v = fmaxf(m_v, __shfl_xor_sync(0xffffffffu, m_v, o));
        m_d = fmaxf(m_d, __shfl_xor_sync(0xffffffffu, m_d, o));
    }
    __shared__ float rmax[NW][3];
    if (lane == 0) { rmax[wid][0] = m_h; rmax[wid][1] = m_v; rmax[wid][2] = m_d; }
    __syncthreads();
    if (tid < 3) {
        float m = rmax[0][tid];
#pragma unroll
        for (int i = 1; i < NW; i++) m = fmaxf(m, rmax[i][tid]);
        atomicMax((int*)&g_max[(BB + tid) * NC + nc], __float_as_int(m));
    }
}

// ================= synthesis: sub-strip + width-split, column IDWT =========
// Block = TM output rows x TWB output cols.  NG = (TM/2)/PR groups of columns,
// each thread owns (group, local coeff col) with an RWH-row register window.
// PA=true : bands from P4 = (a,h,v,d).   PA=false: HV (float2), D, A planes.
// CCP pads the smem row stride to an EVEN float count (round-11 misalign fix).
template<int Hc, int Wc, int H, int W, int BB, int BLK, bool PA,
         int TM, int PR, int TWB>
__global__ void __launch_bounds__(BLK) idwt2_strip(
        const float4* __restrict__ P4,  const float2* __restrict__ HV,
        const float* __restrict__ Dp,   const float* __restrict__ Ap,
        float* __restrict__ outd) {
    constexpr int RWH = PR + 3;                    // coeff rows per group
    constexpr int NG  = (TM / 2) / PR;             // groups
    constexpr int CC  = (TWB / 2 + 3 < Wc) ? TWB / 2 + 3 : Wc;  // logical coeff cols
    constexpr int CCP = (CC + 1) & ~1;             // even row stride for float2 LDS
    constexpr int NW  = BLK / 32;
    __shared__ __align__(16) float slo[TM][CCP];
    __shared__ __align__(16) float shi[TM][CCP];

    const int w0  = blockIdx.x * TWB;
    const int c0  = w0 >> 1;
    const int m0  = blockIdx.y * TM;
    const int nc  = blockIdx.z;
    const int tid = threadIdx.x;
    const float th = 0.3f * g_max[(BB + 0) * NC + nc];
    const float tv = 0.3f * g_max[(BB + 1) * NC + nc];
    const float td = 0.3f * g_max[(BB + 2) * NC + nc];

    // Phase A: NG*CC active threads; one independent vector-load batch each.
    if (tid < NG * CC) {
        const int g  = tid / CC;
        const int j  = tid - g * CC;
        const int pb = g * PR;
        const int qs = (m0 >> 1) + pb;
        const int cg = min(c0 + j, Wc - 1);        // clamped col feeds only masked outputs
        const size_t cb = (size_t)nc * Hc * Wc;

        float Aw[RWH], Hw[RWH], Vw[RWH], Dw[RWH];
        if constexpr (PA) {
            float4 Cw[RWH];
#pragma unroll
            for (int i = 0; i < RWH; i++) {
                int q = min(qs + i, Hc - 1);       // clamped rows feed only masked outputs
                Cw[i] = P4[cb + (unsigned)q * Wc + cg];
            }
#pragma unroll
            for (int i = 0; i < RWH; i++) {
                Aw[i] = Cw[i].x;
                Hw[i] = soft(Cw[i].y, th);
                Vw[i] = soft(Cw[i].z, tv);
                Dw[i] = soft(Cw[i].w, td);
            }
        } else {
            float2 hv[RWH]; float dv[RWH], av[RWH];
#pragma unroll
            for (int i = 0; i < RWH; i++) {
                int q = min(qs + i, Hc - 1);
                size_t o = cb + (unsigned)q * Wc + cg;
                hv[i] = HV[o];
                dv[i] = Dp[o];
                av[i] = Ap[o];
            }
#pragma unroll
            for (int i = 0; i < RWH; i++) {
                Aw[i] = av[i];
                Hw[i] = soft(hv[i].x, th);
                Vw[i] = soft(hv[i].y, tv);
                Dw[i] = soft(dv[i], td);
            }
        }
#pragma unroll
        for (int pp = 0; pp < PR; pp++) {
            const int ml = 2 * (pb + pp);          // strip-local even output row
            float e_lo = 0.f, o_lo = 0.f, e_hi = 0.f, o_hi = 0.f;
#pragma unroll
            for (int i = 0; i < 4; i++) {
                e_lo = fmaf(Aw[pp + i], CLO[6 - 2 * i], fmaf(Hw[pp + i], CHI[6 - 2 * i], e_lo));
                o_lo = fmaf(Aw[pp + i], CLO[7 - 2 * i], fmaf(Hw[pp + i], CHI[7 - 2 * i], o_lo));
                e_hi = fmaf(Vw[pp + i], CLO[6 - 2 * i], fmaf(Dw[pp + i], CHI[6 - 2 * i], e_hi));
                o_hi = fmaf(Vw[pp + i], CLO[7 - 2 * i], fmaf(Dw[pp + i], CHI[7 - 2 * i], o_hi));
            }
            slo[ml][j]     = e_lo;
            slo[ml + 1][j] = o_lo;
            shi[ml][j]     = e_hi;
            shi[ml + 1][j] = o_hi;
        }
    }
    __syncthreads();

    // Phase B: row IDWT; 2 output pairs (4 pixels) per thread, float2 stores.
    const int wid = tid >> 5, lane = tid & 31;
    const int we  = (w0 + TWB < W) ? w0 + TWB : W;
    const int NPb  = (we - w0) >> 1;               // output pairs (may be odd)
    const int NPPb = (NPb + 1) >> 1;
    for (int rr = wid; rr < TM; rr += NW) {
        int m = m0 + rr;
        if (m >= H) break;
        float* od = outd + (size_t)nc * H * W + (size_t)m * W + w0;
        for (int wp2 = lane; wp2 < NPPb; wp2 += 32) {
            const int wp = 2 * wp2;
            float2 l01 = *(const float2*)&slo[rr][wp];
            float2 l23 = *(const float2*)&slo[rr][wp + 2];
            float2 h01 = *(const float2*)&shi[rr][wp];
            float2 h23 = *(const float2*)&shi[rr][wp + 2];
            float ae0 = fmaf(l01.x, CLO[6], fmaf(l01.y, CLO[4], fmaf(l23.x, CLO[2], fmaf(l23.y, CLO[0],
                        fmaf(h01.x, CHI[6], fmaf(h01.y, CHI[4], fmaf(h23.x, CHI[2], h23.y * CHI[0])))))));
            float ao0 = fmaf(l01.x, CLO[7], fmaf(l01.y, CLO[5], fmaf(l23.x, CLO[3], fmaf(l23.y, CLO[1],
                        fmaf(h01.x, CHI[7], fmaf(h01.y, CHI[5], fmaf(h23.x, CHI[3], h23.y * CHI[1])))))));
            *(float2*)&od[2 * wp] = make_float2(ae0, ao0);
            if (wp + 1 < NPb) {
                float l4 = (wp + 4 < CC) ? slo[rr][wp + 4] : 0.f;
                float h4 = (wp + 4 < CC) ? shi[rr][wp + 4] : 0.f;
                float ae1 = fmaf(l01.y, CLO[6], fmaf(l23.x, CLO[4], fmaf(l23.y, CLO[2], fmaf(l4, CLO[0],
                            fmaf(h01.y, CHI[6], fmaf(h23.x, CHI[4], fmaf(h23.y, CHI[2], h4 * CHI[0])))))));
                float ao1 = fmaf(l01.y, CLO[7], fmaf(l23.x, CLO[5], fmaf(l23.y, CLO[3], fmaf(l4, CLO[1],
                            fmaf(h01.y, CHI[7], fmaf(h23.x, CHI[5], fmaf(h23.y, CHI[3], h4 * CHI[1])))))));
                *(float2*)&od[2 * wp + 2] = make_float2(ae1, ao1);
            }
        }
    }
}

// ---------------- host ----------------
static inline unsigned cdiv(unsigned a, unsigned b) { return (a + b - 1) / b; }

extern "C" void kernel_launch(void* const* d_in, const int* in_sizes, int n_in,
                              void* d_out, int out_size) {
    (void)in_sizes; (void)n_in; (void)out_size;
    const float* x = (const float*)d_in[0];
    float* out = (float*)d_out;

    float  *a1, *a1r, *d1;
    float2 *hv1;
    float4 *p2;
    cudaGetSymbolAddress((void**)&a1,  g_a1);
    cudaGetSymbolAddress((void**)&a1r, g_a1r);
    cudaGetSymbolAddress((void**)&d1,  g_d1);
    cudaGetSymbolAddress((void**)&hv1, g_hv1);
    cudaGetSymbolAddress((void**)&p2,  g_p2);

    init_max<<<1, 576>>>();

    // Level-1 analysis: x -> a1 + hv1 + d1 (+ absmax bands 0..2)
    dwt2_strip<S0, S0, S1, S1, 0, 512, true><<<dim3(cdiv(S1, 8), NC), 512>>>(
        x, a1, hv1, d1, nullptr);

    // Level-2 analysis: a1 -> p2 (a,h,v,d) (+ absmax bands 3..5)
    dwt2_strip<S1, S1, S2, S2, 3, 288, false><<<dim3(cdiv(S2, 8), NC), 288>>>(
        a1, nullptr, nullptr, nullptr, p2);

    // Level-2 synthesis: p2 -> a1r.  TM=8, PR=2 halves (5-row window), no width split.
    idwt2_strip<S2, S2, S1, S1, 3, 288, true, 8, 2, S1><<<dim3(1, cdiv(S1, 8), NC), 288>>>(
        p2, nullptr, nullptr, nullptr, a1r);

    // Level-1 synthesis: (a1r, hv1, d1) -> out.  TM=16, PR=4, width split x2 (TWB=256).
    idwt2_strip<S1, S1, S0, S0, 0, 288, false, 16, 4, 256><<<dim3(2, cdiv(S0, 16), NC), 288>>>(
        nullptr, hv1, d1, a1r, out);
}

// round 13
// speedup vs baseline: 1.9652x; 1.0708x over previous
#include <cuda_runtime.h>
#include <cuda_bf16.h>
#include <cuda_fp16.h>

// ---------------- problem constants ----------------
#define NC 96          // B*C = 32*3
#define S0 510
#define S1 258         // (510+7)/2
#define S2 132         // (258+7)/2

// ---------------- static scratch ----------------
__device__ float   g_a1 [NC * S1 * S1];  // dense a1   (dwt1 out -> dwt2 in), fp32
__device__ float   g_a1r[NC * S1 * S1];  // dense a1r  (idwt2 out -> idwt1 in), fp32
__device__ __half2 g_hv1[NC * S1 * S1];  // level-1 (h,v) packed, fp16
__device__ __half  g_d1 [NC * S1 * S1];  // level-1 d plane, fp16
__device__ float4  g_p2 [NC * S2 * S2];  // level-2 packed (x=a, y=h, z=v, w=d), fp32
__device__ float   g_max[6 * NC];        // bands: 0..2 = h1,v1,d1 ; 3..5 = h2,v2,d2

// db4 filters (verified round 1)
__constant__ float CLO[8] = {
     0.23037781330885523f,  0.7148465705525415f,   0.6308807679295904f,
    -0.02798376941698385f, -0.18703481171888114f,  0.030841381835986965f,
     0.032883011666982945f,-0.010597401784997278f };
__constant__ float CHI[8] = {
    -0.010597401784997278f,-0.032883011666982945f, 0.030841381835986965f,
     0.18703481171888114f, -0.02798376941698385f, -0.6308807679295904f,
     0.7148465705525415f,  -0.23037781330885523f };

__device__ __forceinline__ int reflect(int idx, int S) {
    if (idx < 0)  return -1 - idx;
    if (idx >= S) return 2 * S - 1 - idx;
    return idx;
}

__device__ __forceinline__ float soft(float x, float t) {
    return copysignf(fmaxf(fabsf(x) * 1.5f - t, 0.f), x);
}

__global__ void init_max() {
    int i = threadIdx.x;
    if (i < 6 * NC) g_max[i] = 0.f;
}

// ================= analysis: full-width strip, column DWT in registers =====
// Band mapping (fixed round 5): h-band <- rowLO(colHI)=vv ; v-band <- rowHI(colLO)=vh.
// LEVEL1: aplane fp32 dense; hvplane half2 (h,v); dplane half.
// !LEVEL1: packed = (a,h,v,d) float4.
template<int H, int W, int Hc, int Wc, int BB, int BLK, bool LEVEL1>
__global__ void __launch_bounds__(BLK) dwt2_strip(
        const float* __restrict__ x,
        float* __restrict__ aplane, __half2* __restrict__ hvplane,
        __half* __restrict__ dplane, float4* __restrict__ packed) {
    constexpr int TKH = 8;
    constexpr int RN  = 2 * TKH + 6;   // 22 input rows per strip
    constexpr int WPAD = W + 12;       // 6 halo each side (even)
    constexpr int NW  = BLK / 32;
    constexpr int WPR = (NW >= TKH) ? NW / TKH : 1;   // warps per coeff row
    __shared__ __align__(16) float sclo[TKH][WPAD];
    __shared__ __align__(16) float schi[TKH][WPAD];

    const int kh0 = blockIdx.x * TKH;
    const int nc  = blockIdx.y;
    const int tid = threadIdx.x;
    const float* xp = x + (size_t)nc * H * W;

    // Phase A: column DWT, one input column per thread (single pass: BLK >= W).
    for (int c = tid; c < W; c += BLK) {
        float xv[RN];
        const int r0 = 2 * kh0 - 6;
#pragma unroll
        for (int rr = 0; rr < RN; rr++) {
            int r = reflect(r0 + rr, H);
            xv[rr] = xp[(size_t)r * W + c];
        }
#pragma unroll
        for (int khl = 0; khl < TKH; khl++) {
            float al = 0.f, ah = 0.f;
#pragma unroll
            for (int t = 0; t < 8; t++) {
                float v = xv[2 * khl + t];
                al = fmaf(v, CLO[t], al);
                ah = fmaf(v, CHI[t], ah);
            }
            sclo[khl][6 + c] = al;
            schi[khl][6 + c] = ah;
        }
    }
    __syncthreads();

    // Halo fill: horizontal reflection commutes with the column transform.
    if (tid < 12 * TKH) {
        int hc = tid % 12, khl = tid / 12;
        int c   = (hc < 6) ? hc - 6 : W + (hc - 6);
        int src = (c < 0) ? -1 - c : 2 * W - 1 - c;
        sclo[khl][6 + c] = sclo[khl][6 + src];
        schi[khl][6 + c] = schi[khl][6 + src];
    }
    __syncthreads();

    // Phase B: row DWT; 2 coefficients per thread, vector stores.
    const int wid = tid >> 5, lane = tid & 31;
    const int row = wid / WPR, sub = wid % WPR;
    float m_h = 0.f, m_v = 0.f, m_d = 0.f;
    if (row < TKH) {
        const int kh = kh0 + row;
        if (kh < Hc) {
            const float2* plo = (const float2*)(&sclo[row][0]);
            const float2* phi = (const float2*)(&schi[row][0]);
            const unsigned ob = ((unsigned)nc * Hc + kh) * Wc;
            for (int k2 = lane + 32 * sub; k2 < Wc / 2; k2 += 32 * WPR) {
                const int k = 2 * k2;
                float2 l0 = plo[k],     l1 = plo[k + 1], l2 = plo[k + 2];
                float2 l3 = plo[k + 3], l4 = plo[k + 4];
                float2 h0 = phi[k],     h1 = phi[k + 1], h2 = phi[k + 2];
                float2 h3 = phi[k + 3], h4 = phi[k + 4];
                float va0, vh0, vv0, vd0, va1, vh1, vv1, vd1;
                va0 = fmaf(l0.x, CLO[0], fmaf(l0.y, CLO[1], fmaf(l1.x, CLO[2], fmaf(l1.y, CLO[3],
                      fmaf(l2.x, CLO[4], fmaf(l2.y, CLO[5], fmaf(l3.x, CLO[6], l3.y * CLO[7])))))));
                vh0 = fmaf(l0.x, CHI[0], fmaf(l0.y, CHI[1], fmaf(l1.x, CHI[2], fmaf(l1.y, CHI[3],
                      fmaf(l2.x, CHI[4], fmaf(l2.y, CHI[5], fmaf(l3.x, CHI[6], l3.y * CHI[7])))))));
                vv0 = fmaf(h0.x, CLO[0], fmaf(h0.y, CLO[1], fmaf(h1.x, CLO[2], fmaf(h1.y, CLO[3],
                      fmaf(h2.x, CLO[4], fmaf(h2.y, CLO[5], fmaf(h3.x, CLO[6], h3.y * CLO[7])))))));
                vd0 = fmaf(h0.x, CHI[0], fmaf(h0.y, CHI[1], fmaf(h1.x, CHI[2], fmaf(h1.y, CHI[3],
                      fmaf(h2.x, CHI[4], fmaf(h2.y, CHI[5], fmaf(h3.x, CHI[6], h3.y * CHI[7])))))));
                va1 = fmaf(l1.x, CLO[0], fmaf(l1.y, CLO[1], fmaf(l2.x, CLO[2], fmaf(l2.y, CLO[3],
                      fmaf(l3.x, CLO[4], fmaf(l3.y, CLO[5], fmaf(l4.x, CLO[6], l4.y * CLO[7])))))));
                vh1 = fmaf(l1.x, CHI[0], fmaf(l1.y, CHI[1], fmaf(l2.x, CHI[2], fmaf(l2.y, CHI[3],
                      fmaf(l3.x, CHI[4], fmaf(l3.y, CHI[5], fmaf(l4.x, CHI[6], l4.y * CHI[7])))))));
                vv1 = fmaf(h1.x, CLO[0], fmaf(h1.y, CLO[1], fmaf(h2.x, CLO[2], fmaf(h2.y, CLO[3],
                      fmaf(h3.x, CLO[4], fmaf(h3.y, CLO[5], fmaf(h4.x, CLO[6], h4.y * CLO[7])))))));
                vd1 = fmaf(h1.x, CHI[0], fmaf(h1.y, CHI[1], fmaf(h2.x, CHI[2], fmaf(h2.y, CHI[3],
                      fmaf(h3.x, CHI[4], fmaf(h3.y, CHI[5], fmaf(h4.x, CHI[6], h4.y * CHI[7])))))));
                if constexpr (LEVEL1) {
                    *(float2*)&aplane[ob + k] = make_float2(va0, va1);
                    // (h,v) fp16 pairs for k and k+1 -> one 8B store (ob+k even)
                    __half2 p0 = __floats2half2_rn(vv0, vh0);
                    __half2 p1 = __floats2half2_rn(vv1, vh1);
                    uint2 hv2;
                    hv2.x = *(unsigned*)&p0;
                    hv2.y = *(unsigned*)&p1;
                    *(uint2*)&hvplane[ob + k] = hv2;
                    *(__half2*)&dplane[ob + k] = __floats2half2_rn(vd0, vd1);
                } else {
                    packed[ob + k]     = make_float4(va0, vv0, vh0, vd0);
                    packed[ob + k + 1] = make_float4(va1, vv1, vh1, vd1);
                }
                m_h = fmaxf(m_h, fmaxf(fabsf(vv0), fabsf(vv1)));
                m_v = fmaxf(m_v, fmaxf(fabsf(vh0), fabsf(vh1)));
                m_d = fmaxf(m_d, fmaxf(fabsf(vd0), fabsf(vd1)));
            }
        }
    }

#pragma unroll
    for (int o = 16; o > 0; o >>= 1) {
        m_h = fmaxf(m_h, __shfl_xor_sync(0xffffffffu, m_h, o));
        m_v = fmaxf(m_v, __shfl_xor_sync(0xffffffffu, m_v, o));
        m_d = fmaxf(m_d, __shfl_xor_sync(0xffffffffu, m_d, o));
    }
    __shared__ float rmax[NW][3];
    if (lane == 0) { rmax[wid][0] = m_h; rmax[wid][1] = m_v; rmax[wid][2] = m_d; }
    __syncthreads();
    if (tid < 3) {
        float m = rmax[0][tid];
#pragma unroll
        for (int i = 1; i < NW; i++) m = fmaxf(m, rmax[i][tid]);
        atomicMax((int*)&g_max[(BB + tid) * NC + nc], __float_as_int(m));
    }
}

// ================= synthesis: sub-strip + width-split, column IDWT =========
// PA=true : bands from P4 = (a,h,v,d) fp32.
// PA=false: HV (half2 (h,v)), D (half), A (fp32 a1r).
// CCP pads the smem row stride to an EVEN float count (round-11 misalign fix).
template<int Hc, int Wc, int H, int W, int BB, int BLK, bool PA,
         int TM, int PR, int TWB>
__global__ void __launch_bounds__(BLK) idwt2_strip(
        const float4* __restrict__ P4,  const __half2* __restrict__ HV,
        const __half* __restrict__ Dp,  const float* __restrict__ Ap,
        float* __restrict__ outd) {
    constexpr int RWH = PR + 3;                    // coeff rows per group
    constexpr int NG  = (TM / 2) / PR;             // groups
    constexpr int CC  = (TWB / 2 + 3 < Wc) ? TWB / 2 + 3 : Wc;  // logical coeff cols
    constexpr int CCP = (CC + 1) & ~1;             // even row stride for float2 LDS
    constexpr int NW  = BLK / 32;
    __shared__ __align__(16) float slo[TM][CCP];
    __shared__ __align__(16) float shi[TM][CCP];

    const int w0  = blockIdx.x * TWB;
    const int c0  = w0 >> 1;
    const int m0  = blockIdx.y * TM;
    const int nc  = blockIdx.z;
    const int tid = threadIdx.x;
    const float th = 0.3f * g_max[(BB + 0) * NC + nc];
    const float tv = 0.3f * g_max[(BB + 1) * NC + nc];
    const float td = 0.3f * g_max[(BB + 2) * NC + nc];

    // Phase A: NG*CC active threads; one independent vector-load batch each.
    if (tid < NG * CC) {
        const int g  = tid / CC;
        const int j  = tid - g * CC;
        const int pb = g * PR;
        const int qs = (m0 >> 1) + pb;
        const int cg = min(c0 + j, Wc - 1);        // clamped col feeds only masked outputs
        const size_t cb = (size_t)nc * Hc * Wc;

        float Aw[RWH], Hw[RWH], Vw[RWH], Dw[RWH];
        if constexpr (PA) {
            float4 Cw[RWH];
#pragma unroll
            for (int i = 0; i < RWH; i++) {
                int q = min(qs + i, Hc - 1);       // clamped rows feed only masked outputs
                Cw[i] = P4[cb + (unsigned)q * Wc + cg];
            }
#pragma unroll
            for (int i = 0; i < RWH; i++) {
                Aw[i] = Cw[i].x;
                Hw[i] = soft(Cw[i].y, th);
                Vw[i] = soft(Cw[i].z, tv);
                Dw[i] = soft(Cw[i].w, td);
            }
        } else {
            __half2 hv[RWH]; __half dv[RWH]; float av[RWH];
#pragma unroll
            for (int i = 0; i < RWH; i++) {
                int q = min(qs + i, Hc - 1);
                size_t o = cb + (unsigned)q * Wc + cg;
                hv[i] = HV[o];
                dv[i] = Dp[o];
                av[i] = Ap[o];
            }
#pragma unroll
            for (int i = 0; i < RWH; i++) {
                float2 f = __half22float2(hv[i]);
                Aw[i] = av[i];
                Hw[i] = soft(f.x, th);
                Vw[i] = soft(f.y, tv);
                Dw[i] = soft(__half2float(dv[i]), td);
            }
        }
#pragma unroll
        for (int pp = 0; pp < PR; pp++) {
            const int ml = 2 * (pb + pp);          // strip-local even output row
            float e_lo = 0.f, o_lo = 0.f, e_hi = 0.f, o_hi = 0.f;
#pragma unroll
            for (int i = 0; i < 4; i++) {
                e_lo = fmaf(Aw[pp + i], CLO[6 - 2 * i], fmaf(Hw[pp + i], CHI[6 - 2 * i], e_lo));
                o_lo = fmaf(Aw[pp + i], CLO[7 - 2 * i], fmaf(Hw[pp + i], CHI[7 - 2 * i], o_lo));
                e_hi = fmaf(Vw[pp + i], CLO[6 - 2 * i], fmaf(Dw[pp + i], CHI[6 - 2 * i], e_hi));
                o_hi = fmaf(Vw[pp + i], CLO[7 - 2 * i], fmaf(Dw[pp + i], CHI[7 - 2 * i], o_hi));
            }
            slo[ml][j]     = e_lo;
            slo[ml + 1][j] = o_lo;
            shi[ml][j]     = e_hi;
            shi[ml + 1][j] = o_hi;
        }
    }
    __syncthreads();

    // Phase B: row IDWT; 2 output pairs (4 pixels) per thread, float2 stores.
    const int wid = tid >> 5, lane = tid & 31;
    const int we  = (w0 + TWB < W) ? w0 + TWB : W;
    const int NPb  = (we - w0) >> 1;               // output pairs (may be odd)
    const int NPPb = (NPb + 1) >> 1;
    for (int rr = wid; rr < TM; rr += NW) {
        int m = m0 + rr;
        if (m >= H) break;
        float* od = outd + (size_t)nc * H * W + (size_t)m * W + w0;
        for (int wp2 = lane; wp2 < NPPb; wp2 += 32) {
            const int wp = 2 * wp2;
            float2 l01 = *(const float2*)&slo[rr][wp];
            float2 l23 = *(const float2*)&slo[rr][wp + 2];
            float2 h01 = *(const float2*)&shi[rr][wp];
            float2 h23 = *(const float2*)&shi[rr][wp + 2];
            float ae0 = fmaf(l01.x, CLO[6], fmaf(l01.y, CLO[4], fmaf(l23.x, CLO[2], fmaf(l23.y, CLO[0],
                        fmaf(h01.x, CHI[6], fmaf(h01.y, CHI[4], fmaf(h23.x, CHI[2], h23.y * CHI[0])))))));
            float ao0 = fmaf(l01.x, CLO[7], fmaf(l01.y, CLO[5], fmaf(l23.x, CLO[3], fmaf(l23.y, CLO[1],
                        fmaf(h01.x, CHI[7], fmaf(h01.y, CHI[5], fmaf(h23.x, CHI[3], h23.y * CHI[1])))))));
            *(float2*)&od[2 * wp] = make_float2(ae0, ao0);
            if (wp + 1 < NPb) {
                float l4 = (wp + 4 < CC) ? slo[rr][wp + 4] : 0.f;
                float h4 = (wp + 4 < CC) ? shi[rr][wp + 4] : 0.f;
                float ae1 = fmaf(l01.y, CLO[6], fmaf(l23.x, CLO[4], fmaf(l23.y, CLO[2], fmaf(l4, CLO[0],
                            fmaf(h01.y, CHI[6], fmaf(h23.x, CHI[4], fmaf(h23.y, CHI[2], h4 * CHI[0])))))));
                float ao1 = fmaf(l01.y, CLO[7], fmaf(l23.x, CLO[5], fmaf(l23.y, CLO[3], fmaf(l4, CLO[1],
                            fmaf(h01.y, CHI[7], fmaf(h23.x, CHI[5], fmaf(h23.y, CHI[3], h4 * CHI[1])))))));
                *(float2*)&od[2 * wp + 2] = make_float2(ae1, ao1);
            }
        }
    }
}

// ---------------- host ----------------
static inline unsigned cdiv(unsigned a, unsigned b) { return (a + b - 1) / b; }

extern "C" void kernel_launch(void* const* d_in, const int* in_sizes, int n_in,
                              void* d_out, int out_size) {
    (void)in_sizes; (void)n_in; (void)out_size;
    const float* x = (const float*)d_in[0];
    float* out = (float*)d_out;

    float   *a1, *a1r;
    __half2 *hv1;
    __half  *d1;
    float4  *p2;
    cudaGetSymbolAddress((void**)&a1,  g_a1);
    cudaGetSymbolAddress((void**)&a1r, g_a1r);
    cudaGetSymbolAddress((void**)&d1,  g_d1);
    cudaGetSymbolAddress((void**)&hv1, g_hv1);
    cudaGetSymbolAddress((void**)&p2,  g_p2);

    init_max<<<1, 576>>>();

    // Level-1 analysis: x -> a1 (fp32) + hv1/d1 (fp16) (+ absmax bands 0..2)
    dwt2_strip<S0, S0, S1, S1, 0, 512, true><<<dim3(cdiv(S1, 8), NC), 512>>>(
        x, a1, hv1, d1, nullptr);

    // Level-2 analysis: a1 -> p2 (a,h,v,d fp32) (+ absmax bands 3..5)
    dwt2_strip<S1, S1, S2, S2, 3, 288, false><<<dim3(cdiv(S2, 8), NC), 288>>>(
        a1, nullptr, nullptr, nullptr, p2);

    // Level-2 synthesis: p2 -> a1r.  Round-10 best config: TM=16, PR=4, no split.
    idwt2_strip<S2, S2, S1, S1, 3, 288, true, 16, 4, S1><<<dim3(1, cdiv(S1, 16), NC), 288>>>(
        p2, nullptr, nullptr, nullptr, a1r);

    // Level-1 synthesis: (a1r fp32, hv1/d1 fp16) -> out.  TM=16, PR=4, split x2.
    idwt2_strip<S1, S1, S0, S0, 0, 288, false, 16, 4, 256><<<dim3(2, cdiv(S0, 16), NC), 288>>>(
        nullptr, hv1, d1, a1r, out);
}

// round 14
// speedup vs baseline: 1.9657x; 1.0003x over previous
#include <cuda_runtime.h>
#include <cuda_bf16.h>
#include <cuda_fp16.h>

// ---------------- problem constants ----------------
#define NC 96          // B*C = 32*3
#define S0 510
#define S1 258         // (510+7)/2
#define S2 132         // (258+7)/2

// ---------------- static scratch ----------------
__device__ __half  g_a1 [NC * S1 * S1];  // a1  (dwt1 out -> dwt2 in), fp16
__device__ __half  g_a1r[NC * S1 * S1];  // a1r (idwt2 out -> idwt1 in), fp16
__device__ __half2 g_hv1[NC * S1 * S1];  // level-1 (h,v) packed, fp16
__device__ __half  g_d1 [NC * S1 * S1];  // level-1 d plane, fp16
__device__ float4  g_p2 [NC * S2 * S2];  // level-2 packed (x=a, y=h, z=v, w=d), fp32
__device__ float   g_max[6 * NC];        // bands: 0..2 = h1,v1,d1 ; 3..5 = h2,v2,d2

// db4 filters (verified round 1)
__constant__ float CLO[8] = {
     0.23037781330885523f,  0.7148465705525415f,   0.6308807679295904f,
    -0.02798376941698385f, -0.18703481171888114f,  0.030841381835986965f,
     0.032883011666982945f,-0.010597401784997278f };
__constant__ float CHI[8] = {
    -0.010597401784997278f,-0.032883011666982945f, 0.030841381835986965f,
     0.18703481171888114f, -0.02798376941698385f, -0.6308807679295904f,
     0.7148465705525415f,  -0.23037781330885523f };

__device__ __forceinline__ int reflect(int idx, int S) {
    if (idx < 0)  return -1 - idx;
    if (idx >= S) return 2 * S - 1 - idx;
    return idx;
}

__device__ __forceinline__ float soft(float x, float t) {
    return copysignf(fmaxf(fabsf(x) * 1.5f - t, 0.f), x);
}

__device__ __forceinline__ float ld_as_float(const float* p)  { return *p; }
__device__ __forceinline__ float ld_as_float(const __half* p) { return __half2float(*p); }

__global__ void init_max() {
    int i = threadIdx.x;
    if (i < 6 * NC) g_max[i] = 0.f;
}

// ================= analysis: full-width strip, column DWT in registers =====
// Band mapping (fixed round 5): h-band <- rowLO(colHI)=vv ; v-band <- rowHI(colLO)=vh.
// LEVEL1: aplane fp16; hvplane half2 (h,v); dplane half.   !LEVEL1: packed float4.
template<int H, int W, int Hc, int Wc, int BB, int BLK, bool LEVEL1, typename InT>
__global__ void __launch_bounds__(BLK) dwt2_strip(
        const InT* __restrict__ x,
        __half* __restrict__ aplane, __half2* __restrict__ hvplane,
        __half* __restrict__ dplane, float4* __restrict__ packed) {
    constexpr int TKH = 8;
    constexpr int RN  = 2 * TKH + 6;   // 22 input rows per strip
    constexpr int WPAD = W + 12;       // 6 halo each side (even)
    constexpr int NW  = BLK / 32;
    constexpr int WPR = (NW >= TKH) ? NW / TKH : 1;   // warps per coeff row
    __shared__ __align__(16) float sclo[TKH][WPAD];
    __shared__ __align__(16) float schi[TKH][WPAD];

    const int kh0 = blockIdx.x * TKH;
    const int nc  = blockIdx.y;
    const int tid = threadIdx.x;
    const InT* xp = x + (size_t)nc * H * W;

    // Phase A: column DWT, one input column per thread (single pass: BLK >= W).
    for (int c = tid; c < W; c += BLK) {
        float xv[RN];
        const int r0 = 2 * kh0 - 6;
#pragma unroll
        for (int rr = 0; rr < RN; rr++) {
            int r = reflect(r0 + rr, H);
            xv[rr] = ld_as_float(&xp[(size_t)r * W + c]);
        }
#pragma unroll
        for (int khl = 0; khl < TKH; khl++) {
            float al = 0.f, ah = 0.f;
#pragma unroll
            for (int t = 0; t < 8; t++) {
                float v = xv[2 * khl + t];
                al = fmaf(v, CLO[t], al);
                ah = fmaf(v, CHI[t], ah);
            }
            sclo[khl][6 + c] = al;
            schi[khl][6 + c] = ah;
        }
    }
    __syncthreads();

    // Halo fill: horizontal reflection commutes with the column transform.
    if (tid < 12 * TKH) {
        int hc = tid % 12, khl = tid / 12;
        int c   = (hc < 6) ? hc - 6 : W + (hc - 6);
        int src = (c < 0) ? -1 - c : 2 * W - 1 - c;
        sclo[khl][6 + c] = sclo[khl][6 + src];
        schi[khl][6 + c] = schi[khl][6 + src];
    }
    __syncthreads();

    // Phase B: row DWT; 2 coefficients per thread, vector stores.
    const int wid = tid >> 5, lane = tid & 31;
    const int row = wid / WPR, sub = wid % WPR;
    float m_h = 0.f, m_v = 0.f, m_d = 0.f;
    if (row < TKH) {
        const int kh = kh0 + row;
        if (kh < Hc) {
            const float2* plo = (const float2*)(&sclo[row][0]);
            const float2* phi = (const float2*)(&schi[row][0]);
            const unsigned ob = ((unsigned)nc * Hc + kh) * Wc;
            for (int k2 = lane + 32 * sub; k2 < Wc / 2; k2 += 32 * WPR) {
                const int k = 2 * k2;
                float2 l0 = plo[k],     l1 = plo[k + 1], l2 = plo[k + 2];
                float2 l3 = plo[k + 3], l4 = plo[k + 4];
                float2 h0 = phi[k],     h1 = phi[k + 1], h2 = phi[k + 2];
                float2 h3 = phi[k + 3], h4 = phi[k + 4];
                float va0, vh0, vv0, vd0, va1, vh1, vv1, vd1;
                va0 = fmaf(l0.x, CLO[0], fmaf(l0.y, CLO[1], fmaf(l1.x, CLO[2], fmaf(l1.y, CLO[3],
                      fmaf(l2.x, CLO[4], fmaf(l2.y, CLO[5], fmaf(l3.x, CLO[6], l3.y * CLO[7])))))));
                vh0 = fmaf(l0.x, CHI[0], fmaf(l0.y, CHI[1], fmaf(l1.x, CHI[2], fmaf(l1.y, CHI[3],
                      fmaf(l2.x, CHI[4], fmaf(l2.y, CHI[5], fmaf(l3.x, CHI[6], l3.y * CHI[7])))))));
                vv0 = fmaf(h0.x, CLO[0], fmaf(h0.y, CLO[1], fmaf(h1.x, CLO[2], fmaf(h1.y, CLO[3],
                      fmaf(h2.x, CLO[4], fmaf(h2.y, CLO[5], fmaf(h3.x, CLO[6], h3.y * CLO[7])))))));
                vd0 = fmaf(h0.x, CHI[0], fmaf(h0.y, CHI[1], fmaf(h1.x, CHI[2], fmaf(h1.y, CHI[3],
                      fmaf(h2.x, CHI[4], fmaf(h2.y, CHI[5], fmaf(h3.x, CHI[6], h3.y * CHI[7])))))));
                va1 = fmaf(l1.x, CLO[0], fmaf(l1.y, CLO[1], fmaf(l2.x, CLO[2], fmaf(l2.y, CLO[3],
                      fmaf(l3.x, CLO[4], fmaf(l3.y, CLO[5], fmaf(l4.x, CLO[6], l4.y * CLO[7])))))));
                vh1 = fmaf(l1.x, CHI[0], fmaf(l1.y, CHI[1], fmaf(l2.x, CHI[2], fmaf(l2.y, CHI[3],
                      fmaf(l3.x, CHI[4], fmaf(l3.y, CHI[5], fmaf(l4.x, CHI[6], l4.y * CHI[7])))))));
                vv1 = fmaf(h1.x, CLO[0], fmaf(h1.y, CLO[1], fmaf(h2.x, CLO[2], fmaf(h2.y, CLO[3],
                      fmaf(h3.x, CLO[4], fmaf(h3.y, CLO[5], fmaf(h4.x, CLO[6], h4.y * CLO[7])))))));
                vd1 = fmaf(h1.x, CHI[0], fmaf(h1.y, CHI[1], fmaf(h2.x, CHI[2], fmaf(h2.y, CHI[3],
                      fmaf(h3.x, CHI[4], fmaf(h3.y, CHI[5], fmaf(h4.x, CHI[6], h4.y * CHI[7])))))));
                if constexpr (LEVEL1) {
                    *(__half2*)&aplane[ob + k] = __floats2half2_rn(va0, va1);
                    __half2 p0 = __floats2half2_rn(vv0, vh0);
                    __half2 p1 = __floats2half2_rn(vv1, vh1);
                    uint2 hv2;
                    hv2.x = *(unsigned*)&p0;
                    hv2.y = *(unsigned*)&p1;
                    *(uint2*)&hvplane[ob + k] = hv2;
                    *(__half2*)&dplane[ob + k] = __floats2half2_rn(vd0, vd1);
                } else {
                    packed[ob + k]     = make_float4(va0, vv0, vh0, vd0);
                    packed[ob + k + 1] = make_float4(va1, vv1, vh1, vd1);
                }
                m_h = fmaxf(m_h, fmaxf(fabsf(vv0), fabsf(vv1)));
                m_v = fmaxf(m_v, fmaxf(fabsf(vh0), fabsf(vh1)));
                m_d = fmaxf(m_d, fmaxf(fabsf(vd0), fabsf(vd1)));
            }
        }
    }

#pragma unroll
    for (int o = 16; o > 0; o >>= 1) {
        m_h = fmaxf(m_h, __shfl_xor_sync(0xffffffffu, m_h, o));
        m_v = fmaxf(m_v, __shfl_xor_sync(0xffffffffu, m_v, o));
        m_d = fmaxf(m_d, __shfl_xor_sync(0xffffffffu, m_d, o));
    }
    __shared__ float rmax[NW][3];
    if (lane == 0) { rmax[wid][0] = m_h; rmax[wid][1] = m_v; rmax[wid][2] = m_d; }
    __syncthreads();
    if (tid < 3) {
        float m = rmax[0][tid];
#pragma unroll
        for (int i = 1; i < NW; i++) m = fmaxf(m, rmax[i][tid]);
        atomicMax((int*)&g_max[(BB + tid) * NC + nc], __float_as_int(m));
    }
}

// ================= synthesis: sub-strip + width-split, column IDWT =========
// PA=true : bands from P4 = (a,h,v,d) fp32; output OutT (fp16 a1r).
// PA=false: HV (half2), D (half), A (fp16 a1r); output fp32 (final).
template<int Hc, int Wc, int H, int W, int BB, int BLK, bool PA,
         int TM, int PR, int TWB, typename OutT>
__global__ void __launch_bounds__(BLK) idwt2_strip(
        const float4* __restrict__ P4,  const __half2* __restrict__ HV,
        const __half* __restrict__ Dp,  const __half* __restrict__ Ap,
        OutT* __restrict__ outd) {
    constexpr int RWH = PR + 3;                    // coeff rows per group
    constexpr int NG  = (TM / 2) / PR;             // groups
    constexpr int CC  = (TWB / 2 + 3 < Wc) ? TWB / 2 + 3 : Wc;  // logical coeff cols
    constexpr int CCP = (CC + 1) & ~1;             // even row stride for float2 LDS
    constexpr int NW  = BLK / 32;
    __shared__ __align__(16) float slo[TM][CCP];
    __shared__ __align__(16) float shi[TM][CCP];

    const int w0  = blockIdx.x * TWB;
    const int c0  = w0 >> 1;
    const int m0  = blockIdx.y * TM;
    const int nc  = blockIdx.z;
    const int tid = threadIdx.x;
    const float th = 0.3f * g_max[(BB + 0) * NC + nc];
    const float tv = 0.3f * g_max[(BB + 1) * NC + nc];
    const float td = 0.3f * g_max[(BB + 2) * NC + nc];

    // Phase A: NG*CC active threads; one independent vector-load batch each.
    if (tid < NG * CC) {
        const int g  = tid / CC;
        const int j  = tid - g * CC;
        const int pb = g * PR;
        const int qs = (m0 >> 1) + pb;
        const int cg = min(c0 + j, Wc - 1);        // clamped col feeds only masked outputs
        const size_t cb = (size_t)nc * Hc * Wc;

        float Aw[RWH], Hw[RWH], Vw[RWH], Dw[RWH];
        if constexpr (PA) {
            float4 Cw[RWH];
#pragma unroll
            for (int i = 0; i < RWH; i++) {
                int q = min(qs + i, Hc - 1);       // clamped rows feed only masked outputs
                Cw[i] = P4[cb + (unsigned)q * Wc + cg];
            }
#pragma unroll
            for (int i = 0; i < RWH; i++) {
                Aw[i] = Cw[i].x;
                Hw[i] = soft(Cw[i].y, th);
                Vw[i] = soft(Cw[i].z, tv);
                Dw[i] = soft(Cw[i].w, td);
            }
        } else {
            __half2 hv[RWH]; __half dv[RWH], av[RWH];
#pragma unroll
            for (int i = 0; i < RWH; i++) {
                int q = min(qs + i, Hc - 1);
                size_t o = cb + (unsigned)q * Wc + cg;
                hv[i] = HV[o];
                dv[i] = Dp[o];
                av[i] = Ap[o];
            }
#pragma unroll
            for (int i = 0; i < RWH; i++) {
                float2 f = __half22float2(hv[i]);
                Aw[i] = __half2float(av[i]);
                Hw[i] = soft(f.x, th);
                Vw[i] = soft(f.y, tv);
                Dw[i] = soft(__half2float(dv[i]), td);
            }
        }
#pragma unroll
        for (int pp = 0; pp < PR; pp++) {
            const int ml = 2 * (pb + pp);          // strip-local even output row
            float e_lo = 0.f, o_lo = 0.f, e_hi = 0.f, o_hi = 0.f;
#pragma unroll
            for (int i = 0; i < 4; i++) {
                e_lo = fmaf(Aw[pp + i], CLO[6 - 2 * i], fmaf(Hw[pp + i], CHI[6 - 2 * i], e_lo));
                o_lo = fmaf(Aw[pp + i], CLO[7 - 2 * i], fmaf(Hw[pp + i], CHI[7 - 2 * i], o_lo));
                e_hi = fmaf(Vw[pp + i], CLO[6 - 2 * i], fmaf(Dw[pp + i], CHI[6 - 2 * i], e_hi));
                o_hi = fmaf(Vw[pp + i], CLO[7 - 2 * i], fmaf(Dw[pp + i], CHI[7 - 2 * i], o_hi));
            }
            slo[ml][j]     = e_lo;
            slo[ml + 1][j] = o_lo;
            shi[ml][j]     = e_hi;
            shi[ml + 1][j] = o_hi;
        }
    }
    __syncthreads();

    // Phase B: row IDWT; 2 output pairs (4 pixels) per thread, vector stores.
    const int wid = tid >> 5, lane = tid & 31;
    const int we  = (w0 + TWB < W) ? w0 + TWB : W;
    const int NPb  = (we - w0) >> 1;               // output pairs (may be odd)
    const int NPPb = (NPb + 1) >> 1;
    for (int rr = wid; rr < TM; rr += NW) {
        int m = m0 + rr;
        if (m >= H) break;
        OutT* od = outd + (size_t)nc * H * W + (size_t)m * W + w0;
        for (int wp2 = lane; wp2 < NPPb; wp2 += 32) {
            const int wp = 2 * wp2;
            float2 l01 = *(const float2*)&slo[rr][wp];
            float2 l23 = *(const float2*)&slo[rr][wp + 2];
            float2 h01 = *(const float2*)&shi[rr][wp];
            float2 h23 = *(const float2*)&shi[rr][wp + 2];
            float ae0 = fmaf(l01.x, CLO[6], fmaf(l01.y, CLO[4], fmaf(l23.x, CLO[2], fmaf(l23.y, CLO[0],
                        fmaf(h01.x, CHI[6], fmaf(h01.y, CHI[4], fmaf(h23.x, CHI[2], h23.y * CHI[0])))))));
            float ao0 = fmaf(l01.x, CLO[7], fmaf(l01.y, CLO[5], fmaf(l23.x, CLO[3], fmaf(l23.y, CLO[1],
                        fmaf(h01.x, CHI[7], fmaf(h01.y, CHI[5], fmaf(h23.x, CHI[3], h23.y * CHI[1])))))));
            if constexpr (sizeof(OutT) == 2) {
                *(__half2*)&od[2 * wp] = __floats2half2_rn(ae0, ao0);
            } else {
                *(float2*)&od[2 * wp] = make_float2(ae0, ao0);
            }
            if (wp + 1 < NPb) {
                float l4 = (wp + 4 < CC) ? slo[rr][wp + 4] : 0.f;
                float h4 = (wp + 4 < CC) ? shi[rr][wp + 4] : 0.f;
                float ae1 = fmaf(l01.y, CLO[6], fmaf(l23.x, CLO[4], fmaf(l23.y, CLO[2], fmaf(l4, CLO[0],
                            fmaf(h01.y, CHI[6], fmaf(h23.x, CHI[4], fmaf(h23.y, CHI[2], h4 * CHI[0])))))));
                float ao1 = fmaf(l01.y, CLO[7], fmaf(l23.x, CLO[5], fmaf(l23.y, CLO[3], fmaf(l4, CLO[1],
                            fmaf(h01.y, CHI[7], fmaf(h23.x, CHI[5], fmaf(h23.y, CHI[3], h4 * CHI[1])))))));
                if constexpr (sizeof(OutT) == 2) {
                    *(__half2*)&od[2 * wp + 2] = __floats2half2_rn(ae1, ao1);
                } else {
                    *(float2*)&od[2 * wp + 2] = make_float2(ae1, ao1);
                }
            }
        }
    }
}

// ---------------- host ----------------
static inline unsigned cdiv(unsigned a, unsigned b) { return (a + b - 1) / b; }

extern "C" void kernel_launch(void* const* d_in, const int* in_sizes, int n_in,
                              void* d_out, int out_size) {
    (void)in_sizes; (void)n_in; (void)out_size;
    const float* x = (const float*)d_in[0];
    float* out = (float*)d_out;

    __half  *a1, *a1r, *d1;
    __half2 *hv1;
    float4  *p2;
    cudaGetSymbolAddress((void**)&a1,  g_a1);
    cudaGetSymbolAddress((void**)&a1r, g_a1r);
    cudaGetSymbolAddress((void**)&d1,  g_d1);
    cudaGetSymbolAddress((void**)&hv1, g_hv1);
    cudaGetSymbolAddress((void**)&p2,  g_p2);

    init_max<<<1, 576>>>();

    // Level-1 analysis: x (fp32) -> a1/hv1/d1 (fp16) (+ absmax bands 0..2)
    dwt2_strip<S0, S0, S1, S1, 0, 512, true, float><<<dim3(cdiv(S1, 8), NC), 512>>>(
        x, a1, hv1, d1, nullptr);

    // Level-2 analysis: a1 (fp16) -> p2 (fp32) (+ absmax bands 3..5)
    dwt2_strip<S1, S1, S2, S2, 3, 288, false, __half><<<dim3(cdiv(S2, 8), NC), 288>>>(
        a1, nullptr, nullptr, nullptr, p2);

    // Level-2 synthesis: p2 -> a1r (fp16).  TM=16, PR=4, no split.
    idwt2_strip<S2, S2, S1, S1, 3, 288, true, 16, 4, S1, __half>
        <<<dim3(1, cdiv(S1, 16), NC), 288>>>(p2, nullptr, nullptr, nullptr, a1r);

    // Level-1 synthesis: (a1r/hv1/d1 fp16) -> out (fp32).  TM=16, PR=4, split x2.
    idwt2_strip<S1, S1, S0, S0, 0, 288, false, 16, 4, 256, float>
        <<<dim3(2, cdiv(S0, 16), NC), 288>>>(nullptr, hv1, d1, a1r, out);
}

// round 15
// speedup vs baseline: 1.9663x; 1.0003x over previous
#include <cuda_runtime.h>
#include <cuda_bf16.h>
#include <cuda_fp16.h>

// ---------------- problem constants ----------------
#define NC 96          // B*C = 32*3
#define S0 510
#define S1 258         // (510+7)/2
#define S2 132         // (258+7)/2

// ---------------- static scratch ----------------
__device__ __half  g_a1 [NC * S1 * S1];  // a1  (dwt1 out -> dwt2 in), fp16
__device__ __half  g_a1r[NC * S1 * S1];  // a1r (idwt2 out -> idwt1 in), fp16
__device__ __half2 g_hv1[NC * S1 * S1];  // level-1 (h,v) packed, fp16
__device__ __half  g_d1 [NC * S1 * S1];  // level-1 d plane, fp16
__device__ float4  g_p2 [NC * S2 * S2];  // level-2 packed (x=a, y=h, z=v, w=d), fp32
__device__ float   g_max[6 * NC];        // bands: 0..2 = h1,v1,d1 ; 3..5 = h2,v2,d2

// db4 filters (verified round 1)
__constant__ float CLO[8] = {
     0.23037781330885523f,  0.7148465705525415f,   0.6308807679295904f,
    -0.02798376941698385f, -0.18703481171888114f,  0.030841381835986965f,
     0.032883011666982945f,-0.010597401784997278f };
__constant__ float CHI[8] = {
    -0.010597401784997278f,-0.032883011666982945f, 0.030841381835986965f,
     0.18703481171888114f, -0.02798376941698385f, -0.6308807679295904f,
     0.7148465705525415f,  -0.23037781330885523f };

__device__ __forceinline__ int reflect(int idx, int S) {
    if (idx < 0)  return -1 - idx;
    if (idx >= S) return 2 * S - 1 - idx;
    return idx;
}

__device__ __forceinline__ float soft(float x, float t) {
    return copysignf(fmaxf(fabsf(x) * 1.5f - t, 0.f), x);
}

__device__ __forceinline__ float ld_as_float(const float* p)  { return *p; }
__device__ __forceinline__ float ld_as_float(const __half* p) { return __half2float(*p); }
// paired (2 adjacent columns) loads — caller guarantees even column index
__device__ __forceinline__ float2 ld2_as_float2(const float* p)  { return *(const float2*)p; }
__device__ __forceinline__ float2 ld2_as_float2(const __half* p) { return __half22float2(*(const __half2*)p); }

__global__ void init_max() {
    int i = threadIdx.x;
    if (i < 6 * NC) g_max[i] = 0.f;
}

// ================= analysis: full-width strip, column DWT in registers =====
// Band mapping (fixed round 5): h-band <- rowLO(colHI)=vv ; v-band <- rowHI(colLO)=vh.
// PAIRED: phase A processes 2 adjacent columns per thread (float2/half2 loads).
template<int H, int W, int Hc, int Wc, int BB, int BLK, bool LEVEL1, bool PAIRED,
         typename InT>
__global__ void __launch_bounds__(BLK) dwt2_strip(
        const InT* __restrict__ x,
        __half* __restrict__ aplane, __half2* __restrict__ hvplane,
        __half* __restrict__ dplane, float4* __restrict__ packed) {
    constexpr int TKH = 8;
    constexpr int RN  = 2 * TKH + 6;   // 22 input rows per strip
    constexpr int WPAD = W + 12;       // 6 halo each side (even)
    constexpr int NW  = BLK / 32;
    constexpr int WPR = (NW >= TKH) ? NW / TKH : 1;   // warps per coeff row
    static_assert(NW >= TKH, "phase B needs >= TKH warps");
    __shared__ __align__(16) float sclo[TKH][WPAD];
    __shared__ __align__(16) float schi[TKH][WPAD];

    const int kh0 = blockIdx.x * TKH;
    const int nc  = blockIdx.y;
    const int tid = threadIdx.x;
    const InT* xp = x + (size_t)nc * H * W;
    const int r0 = 2 * kh0 - 6;

    // Phase A: column DWT.
    if constexpr (PAIRED) {
        // 2 adjacent columns per thread; vector loads + vector STS.
        for (int p = tid; p < W / 2; p += BLK) {
            const int c = 2 * p;
            float2 xv[RN];
#pragma unroll
            for (int rr = 0; rr < RN; rr++) {
                int r = reflect(r0 + rr, H);
                xv[rr] = ld2_as_float2(&xp[(size_t)r * W + c]);
            }
#pragma unroll
            for (int khl = 0; khl < TKH; khl++) {
                float al0 = 0.f, ah0 = 0.f, al1 = 0.f, ah1 = 0.f;
#pragma unroll
                for (int t = 0; t < 8; t++) {
                    float2 v = xv[2 * khl + t];
                    al0 = fmaf(v.x, CLO[t], al0);
                    ah0 = fmaf(v.x, CHI[t], ah0);
                    al1 = fmaf(v.y, CLO[t], al1);
                    ah1 = fmaf(v.y, CHI[t], ah1);
                }
                *(float2*)&sclo[khl][6 + c] = make_float2(al0, al1);  // 6+c even -> 8B ok
                *(float2*)&schi[khl][6 + c] = make_float2(ah0, ah1);
            }
        }
    } else {
        for (int c = tid; c < W; c += BLK) {
            float xv[RN];
#pragma unroll
            for (int rr = 0; rr < RN; rr++) {
                int r = reflect(r0 + rr, H);
                xv[rr] = ld_as_float(&xp[(size_t)r * W + c]);
            }
#pragma unroll
            for (int khl = 0; khl < TKH; khl++) {
                float al = 0.f, ah = 0.f;
#pragma unroll
                for (int t = 0; t < 8; t++) {
                    float v = xv[2 * khl + t];
                    al = fmaf(v, CLO[t], al);
                    ah = fmaf(v, CHI[t], ah);
                }
                sclo[khl][6 + c] = al;
                schi[khl][6 + c] = ah;
            }
        }
    }
    __syncthreads();

    // Halo fill: horizontal reflection commutes with the column transform.
    if (tid < 12 * TKH) {
        int hc = tid % 12, khl = tid / 12;
        int c   = (hc < 6) ? hc - 6 : W + (hc - 6);
        int src = (c < 0) ? -1 - c : 2 * W - 1 - c;
        sclo[khl][6 + c] = sclo[khl][6 + src];
        schi[khl][6 + c] = schi[khl][6 + src];
    }
    __syncthreads();

    // Phase B: row DWT; 2 coefficients per thread, vector stores.
    const int wid = tid >> 5, lane = tid & 31;
    const int row = wid / WPR, sub = wid % WPR;
    float m_h = 0.f, m_v = 0.f, m_d = 0.f;
    if (row < TKH) {
        const int kh = kh0 + row;
        if (kh < Hc) {
            const float2* plo = (const float2*)(&sclo[row][0]);
            const float2* phi = (const float2*)(&schi[row][0]);
            const unsigned ob = ((unsigned)nc * Hc + kh) * Wc;
            for (int k2 = lane + 32 * sub; k2 < Wc / 2; k2 += 32 * WPR) {
                const int k = 2 * k2;
                float2 l0 = plo[k],     l1 = plo[k + 1], l2 = plo[k + 2];
                float2 l3 = plo[k + 3], l4 = plo[k + 4];
                float2 h0 = phi[k],     h1 = phi[k + 1], h2 = phi[k + 2];
                float2 h3 = phi[k + 3], h4 = phi[k + 4];
                float va0, vh0, vv0, vd0, va1, vh1, vv1, vd1;
                va0 = fmaf(l0.x, CLO[0], fmaf(l0.y, CLO[1], fmaf(l1.x, CLO[2], fmaf(l1.y, CLO[3],
                      fmaf(l2.x, CLO[4], fmaf(l2.y, CLO[5], fmaf(l3.x, CLO[6], l3.y * CLO[7])))))));
                vh0 = fmaf(l0.x, CHI[0], fmaf(l0.y, CHI[1], fmaf(l1.x, CHI[2], fmaf(l1.y, CHI[3],
                      fmaf(l2.x, CHI[4], fmaf(l2.y, CHI[5], fmaf(l3.x, CHI[6], l3.y * CHI[7])))))));
                vv0 = fmaf(h0.x, CLO[0], fmaf(h0.y, CLO[1], fmaf(h1.x, CLO[2], fmaf(h1.y, CLO[3],
                      fmaf(h2.x, CLO[4], fmaf(h2.y, CLO[5], fmaf(h3.x, CLO[6], h3.y * CLO[7])))))));
                vd0 = fmaf(h0.x, CHI[0], fmaf(h0.y, CHI[1], fmaf(h1.x, CHI[2], fmaf(h1.y, CHI[3],
                      fmaf(h2.x, CHI[4], fmaf(h2.y, CHI[5], fmaf(h3.x, CHI[6], h3.y * CHI[7])))))));
                va1 = fmaf(l1.x, CLO[0], fmaf(l1.y, CLO[1], fmaf(l2.x, CLO[2], fmaf(l2.y, CLO[3],
                      fmaf(l3.x, CLO[4], fmaf(l3.y, CLO[5], fmaf(l4.x, CLO[6], l4.y * CLO[7])))))));
                vh1 = fmaf(l1.x, CHI[0], fmaf(l1.y, CHI[1], fmaf(l2.x, CHI[2], fmaf(l2.y, CHI[3],
                      fmaf(l3.x, CHI[4], fmaf(l3.y, CHI[5], fmaf(l4.x, CHI[6], l4.y * CHI[7])))))));
                vv1 = fmaf(h1.x, CLO[0], fmaf(h1.y, CLO[1], fmaf(h2.x, CLO[2], fmaf(h2.y, CLO[3],
                      fmaf(h3.x, CLO[4], fmaf(h3.y, CLO[5], fmaf(h4.x, CLO[6], h4.y * CLO[7])))))));
                vd1 = fmaf(h1.x, CHI[0], fmaf(h1.y, CHI[1], fmaf(h2.x, CHI[2], fmaf(h2.y, CHI[3],
                      fmaf(h3.x, CHI[4], fmaf(h3.y, CHI[5], fmaf(h4.x, CHI[6], h4.y * CHI[7])))))));
                if constexpr (LEVEL1) {
                    *(__half2*)&aplane[ob + k] = __floats2half2_rn(va0, va1);
                    __half2 p0 = __floats2half2_rn(vv0, vh0);
                    __half2 p1 = __floats2half2_rn(vv1, vh1);
                    uint2 hv2;
                    hv2.x = *(unsigned*)&p0;
                    hv2.y = *(unsigned*)&p1;
                    *(uint2*)&hvplane[ob + k] = hv2;
                    *(__half2*)&dplane[ob + k] = __floats2half2_rn(vd0, vd1);
                } else {
                    packed[ob + k]     = make_float4(va0, vv0, vh0, vd0);
                    packed[ob + k + 1] = make_float4(va1, vv1, vh1, vd1);
                }
                m_h = fmaxf(m_h, fmaxf(fabsf(vv0), fabsf(vv1)));
                m_v = fmaxf(m_v, fmaxf(fabsf(vh0), fabsf(vh1)));
                m_d = fmaxf(m_d, fmaxf(fabsf(vd0), fabsf(vd1)));
            }
        }
    }

#pragma unroll
    for (int o = 16; o > 0; o >>= 1) {
        m_h = fmaxf(m_h, __shfl_xor_sync(0xffffffffu, m_h, o));
        m_v = fmaxf(m_v, __shfl_xor_sync(0xffffffffu, m_v, o));
        m_d = fmaxf(m_d, __shfl_xor_sync(0xffffffffu, m_d, o));
    }
    __shared__ float rmax[NW][3];
    if (lane == 0) { rmax[wid][0] = m_h; rmax[wid][1] = m_v; rmax[wid][2] = m_d; }
    __syncthreads();
    if (tid < 3) {
        float m = rmax[0][tid];
#pragma unroll
        for (int i = 1; i < NW; i++) m = fmaxf(m, rmax[i][tid]);
        atomicMax((int*)&g_max[(BB + tid) * NC + nc], __float_as_int(m));
    }
}

// ================= synthesis: sub-strip + width-split, column IDWT =========
// PA=true : bands from P4 = (a,h,v,d) fp32; output OutT (fp16 a1r).
// PA=false: HV (half2), D (half), A (fp16 a1r); output fp32 (final).
template<int Hc, int Wc, int H, int W, int BB, int BLK, bool PA,
         int TM, int PR, int TWB, typename OutT>
__global__ void __launch_bounds__(BLK) idwt2_strip(
        const float4* __restrict__ P4,  const __half2* __restrict__ HV,
        const __half* __restrict__ Dp,  const __half* __restrict__ Ap,
        OutT* __restrict__ outd) {
    constexpr int RWH = PR + 3;                    // coeff rows per group
    constexpr int NG  = (TM / 2) / PR;             // groups
    constexpr int CC  = (TWB / 2 + 3 < Wc) ? TWB / 2 + 3 : Wc;  // logical coeff cols
    constexpr int CCP = (CC + 1) & ~1;             // even row stride for float2 LDS
    constexpr int NW  = BLK / 32;
    __shared__ __align__(16) float slo[TM][CCP];
    __shared__ __align__(16) float shi[TM][CCP];

    const int w0  = blockIdx.x * TWB;
    const int c0  = w0 >> 1;
    const int m0  = blockIdx.y * TM;
    const int nc  = blockIdx.z;
    const int tid = threadIdx.x;
    const float th = 0.3f * g_max[(BB + 0) * NC + nc];
    const float tv = 0.3f * g_max[(BB + 1) * NC + nc];
    const float td = 0.3f * g_max[(BB + 2) * NC + nc];

    // Phase A: NG*CC active threads; one independent vector-load batch each.
    if (tid < NG * CC) {
        const int g  = tid / CC;
        const int j  = tid - g * CC;
        const int pb = g * PR;
        const int qs = (m0 >> 1) + pb;
        const int cg = min(c0 + j, Wc - 1);        // clamped col feeds only masked outputs
        const size_t cb = (size_t)nc * Hc * Wc;

        float Aw[RWH], Hw[RWH], Vw[RWH], Dw[RWH];
        if constexpr (PA) {
            float4 Cw[RWH];
#pragma unroll
            for (int i = 0; i < RWH; i++) {
                int q = min(qs + i, Hc - 1);       // clamped rows feed only masked outputs
                Cw[i] = P4[cb + (unsigned)q * Wc + cg];
            }
#pragma unroll
            for (int i = 0; i < RWH; i++) {
                Aw[i] = Cw[i].x;
                Hw[i] = soft(Cw[i].y, th);
                Vw[i] = soft(Cw[i].z, tv);
                Dw[i] = soft(Cw[i].w, td);
            }
        } else {
            __half2 hv[RWH]; __half dv[RWH], av[RWH];
#pragma unroll
            for (int i = 0; i < RWH; i++) {
                int q = min(qs + i, Hc - 1);
                size_t o = cb + (unsigned)q * Wc + cg;
                hv[i] = HV[o];
                dv[i] = Dp[o];
                av[i] = Ap[o];
            }
#pragma unroll
            for (int i = 0; i < RWH; i++) {
                float2 f = __half22float2(hv[i]);
                Aw[i] = __half2float(av[i]);
                Hw[i] = soft(f.x, th);
                Vw[i] = soft(f.y, tv);
                Dw[i] = soft(__half2float(dv[i]), td);
            }
        }
#pragma unroll
        for (int pp = 0; pp < PR; pp++) {
            const int ml = 2 * (pb + pp);          // strip-local even output row
            float e_lo = 0.f, o_lo = 0.f, e_hi = 0.f, o_hi = 0.f;
#pragma unroll
            for (int i = 0; i < 4; i++) {
                e_lo = fmaf(Aw[pp + i], CLO[6 - 2 * i], fmaf(Hw[pp + i], CHI[6 - 2 * i], e_lo));
                o_lo = fmaf(Aw[pp + i], CLO[7 - 2 * i], fmaf(Hw[pp + i], CHI[7 - 2 * i], o_lo));
                e_hi = fmaf(Vw[pp + i], CLO[6 - 2 * i], fmaf(Dw[pp + i], CHI[6 - 2 * i], e_hi));
                o_hi = fmaf(Vw[pp + i], CLO[7 - 2 * i], fmaf(Dw[pp + i], CHI[7 - 2 * i], o_hi));
            }
            slo[ml][j]     = e_lo;
            slo[ml + 1][j] = o_lo;
            shi[ml][j]     = e_hi;
            shi[ml + 1][j] = o_hi;
        }
    }
    __syncthreads();

    // Phase B: row IDWT; 2 output pairs (4 pixels) per thread, vector stores.
    // (float4/uint2 widening rejected: W % 4 != 0 makes odd rows 8B-misaligned.)
    const int wid = tid >> 5, lane = tid & 31;
    const int we  = (w0 + TWB < W) ? w0 + TWB : W;
    const int NPb  = (we - w0) >> 1;               // output pairs (may be odd)
    const int NPPb = (NPb + 1) >> 1;
    for (int rr = wid; rr < TM; rr += NW) {
        int m = m0 + rr;
        if (m >= H) break;
        OutT* od = outd + (size_t)nc * H * W + (size_t)m * W + w0;
        for (int wp2 = lane; wp2 < NPPb; wp2 += 32) {
            const int wp = 2 * wp2;
            float2 l01 = *(const float2*)&slo[rr][wp];
            float2 l23 = *(const float2*)&slo[rr][wp + 2];
            float2 h01 = *(const float2*)&shi[rr][wp];
            float2 h23 = *(const float2*)&shi[rr][wp + 2];
            float ae0 = fmaf(l01.x, CLO[6], fmaf(l01.y, CLO[4], fmaf(l23.x, CLO[2], fmaf(l23.y, CLO[0],
                        fmaf(h01.x, CHI[6], fmaf(h01.y, CHI[4], fmaf(h23.x, CHI[2], h23.y * CHI[0])))))));
            float ao0 = fmaf(l01.x, CLO[7], fmaf(l01.y, CLO[5], fmaf(l23.x, CLO[3], fmaf(l23.y, CLO[1],
                        fmaf(h01.x, CHI[7], fmaf(h01.y, CHI[5], fmaf(h23.x, CHI[3], h23.y * CHI[1])))))));
            if constexpr (sizeof(OutT) == 2) {
                *(__half2*)&od[2 * wp] = __floats2half2_rn(ae0, ao0);
            } else {
                *(float2*)&od[2 * wp] = make_float2(ae0, ao0);
            }
            if (wp + 1 < NPb) {
                float l4 = (wp + 4 < CC) ? slo[rr][wp + 4] : 0.f;
                float h4 = (wp + 4 < CC) ? shi[rr][wp + 4] : 0.f;
                float ae1 = fmaf(l01.y, CLO[6], fmaf(l23.x, CLO[4], fmaf(l23.y, CLO[2], fmaf(l4, CLO[0],
                            fmaf(h01.y, CHI[6], fmaf(h23.x, CHI[4], fmaf(h23.y, CHI[2], h4 * CHI[0])))))));
                float ao1 = fmaf(l01.y, CLO[7], fmaf(l23.x, CLO[5], fmaf(l23.y, CLO[3], fmaf(l4, CLO[1],
                            fmaf(h01.y, CHI[7], fmaf(h23.x, CHI[5], fmaf(h23.y, CHI[3], h4 * CHI[1])))))));
                if constexpr (sizeof(OutT) == 2) {
                    *(__half2*)&od[2 * wp + 2] = __floats2half2_rn(ae1, ao1);
                } else {
                    *(float2*)&od[2 * wp + 2] = make_float2(ae1, ao1);
                }
            }
        }
    }
}

// ---------------- host ----------------
static inline unsigned cdiv(unsigned a, unsigned b) { return (a + b - 1) / b; }

extern "C" void kernel_launch(void* const* d_in, const int* in_sizes, int n_in,
                              void* d_out, int out_size) {
    (void)in_sizes; (void)n_in; (void)out_size;
    const float* x = (const float*)d_in[0];
    float* out = (float*)d_out;

    __half  *a1, *a1r, *d1;
    __half2 *hv1;
    float4  *p2;
    cudaGetSymbolAddress((void**)&a1,  g_a1);
    cudaGetSymbolAddress((void**)&a1r, g_a1r);
    cudaGetSymbolAddress((void**)&d1,  g_d1);
    cudaGetSymbolAddress((void**)&hv1, g_hv1);
    cudaGetSymbolAddress((void**)&p2,  g_p2);

    init_max<<<1, 576>>>();

    // Level-1 analysis: x (fp32) -> a1/hv1/d1 (fp16).  PAIRED phase A, 256 thr
    // (255 active pairs; 8 warps -> 1 warp per coeff row in phase B).
    dwt2_strip<S0, S0, S1, S1, 0, 256, true, true, float>
        <<<dim3(cdiv(S1, 8), NC), 256>>>(x, a1, hv1, d1, nullptr);

    // Level-2 analysis: a1 (fp16) -> p2 (fp32).  Single-column phase A, 288 thr.
    dwt2_strip<S1, S1, S2, S2, 3, 288, false, false, __half>
        <<<dim3(cdiv(S2, 8), NC), 288>>>(a1, nullptr, nullptr, nullptr, p2);

    // Level-2 synthesis: p2 -> a1r (fp16).  TM=16, PR=4, no split.
    idwt2_strip<S2, S2, S1, S1, 3, 288, true, 16, 4, S1, __half>
        <<<dim3(1, cdiv(S1, 16), NC), 288>>>(p2, nullptr, nullptr, nullptr, a1r);

    // Level-1 synthesis: (a1r/hv1/d1 fp16) -> out (fp32).  TM=16, PR=4, split x2.
    idwt2_strip<S1, S1, S0, S0, 0, 288, false, 16, 4, 256, float>
        <<<dim3(2, cdiv(S0, 16), NC), 288>>>(nullptr, hv1, d1, a1r, out);
}

// round 16
// speedup vs baseline: 2.0581x; 1.0467x over previous
#include <cuda_runtime.h>
#include <cuda_bf16.h>
#include <cuda_fp16.h>

// ---------------- problem constants ----------------
#define NC 96          // B*C = 32*3
#define S0 510
#define S1 258         // (510+7)/2
#define S2 132         // (258+7)/2

// ---------------- static scratch ----------------
__device__ __half  g_a1 [NC * S1 * S1];  // a1  (dwt1 out -> dwt2 in), fp16
__device__ __half  g_a1r[NC * S1 * S1];  // a1r (idwt2 out -> idwt1 in), fp16
__device__ __half2 g_hv1[NC * S1 * S1];  // level-1 (h,v) packed, fp16
__device__ __half  g_d1 [NC * S1 * S1];  // level-1 d plane, fp16
__device__ float4  g_p2 [NC * S2 * S2];  // level-2 packed (x=a, y=h, z=v, w=d), fp32
__device__ float   g_max[6 * NC];        // bands: 0..2 = h1,v1,d1 ; 3..5 = h2,v2,d2

// db4 filters as compile-time constants (folded to FFMA-imm; Blackwell has no
// cbank ALU operand, so __constant__ arrays forced LDC + register per tap).
__device__ __forceinline__ constexpr float CLOf(int t) {
    return (t == 0) ?  0.23037781330885523f
         : (t == 1) ?  0.7148465705525415f
         : (t == 2) ?  0.6308807679295904f
         : (t == 3) ? -0.02798376941698385f
         : (t == 4) ? -0.18703481171888114f
         : (t == 5) ?  0.030841381835986965f
         : (t == 6) ?  0.032883011666982945f
         :            -0.010597401784997278f;
}
__device__ __forceinline__ constexpr float CHIf(int t) {
    return (t == 0) ? -0.010597401784997278f
         : (t == 1) ? -0.032883011666982945f
         : (t == 2) ?  0.030841381835986965f
         : (t == 3) ?  0.18703481171888114f
         : (t == 4) ? -0.02798376941698385f
         : (t == 5) ? -0.6308807679295904f
         : (t == 6) ?  0.7148465705525415f
         :            -0.23037781330885523f;
}

__device__ __forceinline__ int reflect(int idx, int S) {
    if (idx < 0)  return -1 - idx;
    if (idx >= S) return 2 * S - 1 - idx;
    return idx;
}

__device__ __forceinline__ float soft(float x, float t) {
    return copysignf(fmaxf(fabsf(x) * 1.5f - t, 0.f), x);
}

__device__ __forceinline__ float ld_as_float(const float* p)  { return *p; }
__device__ __forceinline__ float ld_as_float(const __half* p) { return __half2float(*p); }
// paired (2 adjacent columns) loads — caller guarantees even column index
__device__ __forceinline__ float2 ld2_as_float2(const float* p)  { return *(const float2*)p; }
__device__ __forceinline__ float2 ld2_as_float2(const __half* p) { return __half22float2(*(const __half2*)p); }

// ================= analysis: full-width strip, column DWT in registers =====
// Band mapping (fixed round 5): h-band <- rowLO(colHI)=vv ; v-band <- rowHI(colLO)=vh.
// PAIRED: phase A processes 2 adjacent columns per thread (float2/half2 loads).
template<int H, int W, int Hc, int Wc, int BB, int BLK, bool LEVEL1, bool PAIRED,
         typename InT>
__global__ void __launch_bounds__(BLK) dwt2_strip(
        const InT* __restrict__ x,
        __half* __restrict__ aplane, __half2* __restrict__ hvplane,
        __half* __restrict__ dplane, float4* __restrict__ packed) {
    constexpr int TKH = 8;
    constexpr int RN  = 2 * TKH + 6;   // 22 input rows per strip
    constexpr int WPAD = W + 12;       // 6 halo each side (even)
    constexpr int NW  = BLK / 32;
    constexpr int WPR = (NW >= TKH) ? NW / TKH : 1;   // warps per coeff row
    static_assert(NW >= TKH, "phase B needs >= TKH warps");
    __shared__ __align__(16) float sclo[TKH][WPAD];
    __shared__ __align__(16) float schi[TKH][WPAD];

    const int kh0 = blockIdx.x * TKH;
    const int nc  = blockIdx.y;
    const int tid = threadIdx.x;
    const InT* xp = x + (size_t)nc * H * W;
    const int r0 = 2 * kh0 - 6;

    // Phase A: column DWT.
    if constexpr (PAIRED) {
        for (int p = tid; p < W / 2; p += BLK) {
            const int c = 2 * p;
            float2 xv[RN];
#pragma unroll
            for (int rr = 0; rr < RN; rr++) {
                int r = reflect(r0 + rr, H);
                xv[rr] = ld2_as_float2(&xp[(size_t)r * W + c]);
            }
#pragma unroll
            for (int khl = 0; khl < TKH; khl++) {
                float al0 = 0.f, ah0 = 0.f, al1 = 0.f, ah1 = 0.f;
#pragma unroll
                for (int t = 0; t < 8; t++) {
                    float2 v = xv[2 * khl + t];
                    al0 = fmaf(v.x, CLOf(t), al0);
                    ah0 = fmaf(v.x, CHIf(t), ah0);
                    al1 = fmaf(v.y, CLOf(t), al1);
                    ah1 = fmaf(v.y, CHIf(t), ah1);
                }
                *(float2*)&sclo[khl][6 + c] = make_float2(al0, al1);  // 6+c even -> 8B ok
                *(float2*)&schi[khl][6 + c] = make_float2(ah0, ah1);
            }
        }
    } else {
        for (int c = tid; c < W; c += BLK) {
            float xv[RN];
#pragma unroll
            for (int rr = 0; rr < RN; rr++) {
                int r = reflect(r0 + rr, H);
                xv[rr] = ld_as_float(&xp[(size_t)r * W + c]);
            }
#pragma unroll
            for (int khl = 0; khl < TKH; khl++) {
                float al = 0.f, ah = 0.f;
#pragma unroll
                for (int t = 0; t < 8; t++) {
                    float v = xv[2 * khl + t];
                    al = fmaf(v, CLOf(t), al);
                    ah = fmaf(v, CHIf(t), ah);
                }
                sclo[khl][6 + c] = al;
                schi[khl][6 + c] = ah;
            }
        }
    }
    __syncthreads();

    // Halo fill: horizontal reflection commutes with the column transform.
    if (tid < 12 * TKH) {
        int hc = tid % 12, khl = tid / 12;
        int c   = (hc < 6) ? hc - 6 : W + (hc - 6);
        int src = (c < 0) ? -1 - c : 2 * W - 1 - c;
        sclo[khl][6 + c] = sclo[khl][6 + src];
        schi[khl][6 + c] = schi[khl][6 + src];
    }
    __syncthreads();

    // Phase B: row DWT; 2 coefficients per thread, vector stores.
    const int wid = tid >> 5, lane = tid & 31;
    const int row = wid / WPR, sub = wid % WPR;
    float m_h = 0.f, m_v = 0.f, m_d = 0.f;
    if (row < TKH) {
        const int kh = kh0 + row;
        if (kh < Hc) {
            const float2* plo = (const float2*)(&sclo[row][0]);
            const float2* phi = (const float2*)(&schi[row][0]);
            const unsigned ob = ((unsigned)nc * Hc + kh) * Wc;
            for (int k2 = lane + 32 * sub; k2 < Wc / 2; k2 += 32 * WPR) {
                const int k = 2 * k2;
                float2 l0 = plo[k],     l1 = plo[k + 1], l2 = plo[k + 2];
                float2 l3 = plo[k + 3], l4 = plo[k + 4];
                float2 h0 = phi[k],     h1 = phi[k + 1], h2 = phi[k + 2];
                float2 h3 = phi[k + 3], h4 = phi[k + 4];
                float va0, vh0, vv0, vd0, va1, vh1, vv1, vd1;
                va0 = fmaf(l0.x, CLOf(0), fmaf(l0.y, CLOf(1), fmaf(l1.x, CLOf(2), fmaf(l1.y, CLOf(3),
                      fmaf(l2.x, CLOf(4), fmaf(l2.y, CLOf(5), fmaf(l3.x, CLOf(6), l3.y * CLOf(7))))))));
                vh0 = fmaf(l0.x, CHIf(0), fmaf(l0.y, CHIf(1), fmaf(l1.x, CHIf(2), fmaf(l1.y, CHIf(3),
                      fmaf(l2.x, CHIf(4), fmaf(l2.y, CHIf(5), fmaf(l3.x, CHIf(6), l3.y * CHIf(7))))))));
                vv0 = fmaf(h0.x, CLOf(0), fmaf(h0.y, CLOf(1), fmaf(h1.x, CLOf(2), fmaf(h1.y, CLOf(3),
                      fmaf(h2.x, CLOf(4), fmaf(h2.y, CLOf(5), fmaf(h3.x, CLOf(6), h3.y * CLOf(7))))))));
                vd0 = fmaf(h0.x, CHIf(0), fmaf(h0.y, CHIf(1), fmaf(h1.x, CHIf(2), fmaf(h1.y, CHIf(3),
                      fmaf(h2.x, CHIf(4), fmaf(h2.y, CHIf(5), fmaf(h3.x, CHIf(6), h3.y * CHIf(7))))))));
                va1 = fmaf(l1.x, CLOf(0), fmaf(l1.y, CLOf(1), fmaf(l2.x, CLOf(2), fmaf(l2.y, CLOf(3),
                      fmaf(l3.x, CLOf(4), fmaf(l3.y, CLOf(5), fmaf(l4.x, CLOf(6), l4.y * CLOf(7))))))));
                vh1 = fmaf(l1.x, CHIf(0), fmaf(l1.y, CHIf(1), fmaf(l2.x, CHIf(2), fmaf(l2.y, CHIf(3),
                      fmaf(l3.x, CHIf(4), fmaf(l3.y, CHIf(5), fmaf(l4.x, CHIf(6), l4.y * CHIf(7))))))));
                vv1 = fmaf(h1.x, CLOf(0), fmaf(h1.y, CLOf(1), fmaf(h2.x, CLOf(2), fmaf(h2.y, CLOf(3),
                      fmaf(h3.x, CLOf(4), fmaf(h3.y, CLOf(5), fmaf(h4.x, CLOf(6), h4.y * CLOf(7))))))));
                vd1 = fmaf(h1.x, CHIf(0), fmaf(h1.y, CHIf(1), fmaf(h2.x, CHIf(2), fmaf(h2.y, CHIf(3),
                      fmaf(h3.x, CHIf(4), fmaf(h3.y, CHIf(5), fmaf(h4.x, CHIf(6), h4.y * CHIf(7))))))));
                if constexpr (LEVEL1) {
                    *(__half2*)&aplane[ob + k] = __floats2half2_rn(va0, va1);
                    __half2 p0 = __floats2half2_rn(vv0, vh0);
                    __half2 p1 = __floats2half2_rn(vv1, vh1);
                    uint2 hv2;
                    hv2.x = *(unsigned*)&p0;
                    hv2.y = *(unsigned*)&p1;
                    *(uint2*)&hvplane[ob + k] = hv2;
                    *(__half2*)&dplane[ob + k] = __floats2half2_rn(vd0, vd1);
                } else {
                    packed[ob + k]     = make_float4(va0, vv0, vh0, vd0);
                    packed[ob + k + 1] = make_float4(va1, vv1, vh1, vd1);
                }
                m_h = fmaxf(m_h, fmaxf(fabsf(vv0), fabsf(vv1)));
                m_v = fmaxf(m_v, fmaxf(fabsf(vh0), fabsf(vh1)));
                m_d = fmaxf(m_d, fmaxf(fabsf(vd0), fabsf(vd1)));
            }
        }
    }

#pragma unroll
    for (int o = 16; o > 0; o >>= 1) {
        m_h = fmaxf(m_h, __shfl_xor_sync(0xffffffffu, m_h, o));
        m_v = fmaxf(m_v, __shfl_xor_sync(0xffffffffu, m_v, o));
        m_d = fmaxf(m_d, __shfl_xor_sync(0xffffffffu, m_d, o));
    }
    __shared__ float rmax[NW][3];
    if (lane == 0) { rmax[wid][0] = m_h; rmax[wid][1] = m_v; rmax[wid][2] = m_d; }
    __syncthreads();
    if (tid < 3) {
        float m = rmax[0][tid];
#pragma unroll
        for (int i = 1; i < NW; i++) m = fmaxf(m, rmax[i][tid]);
        atomicMax((int*)&g_max[(BB + tid) * NC + nc], __float_as_int(m));
    }
}

// ================= synthesis: sub-strip + width-split, column IDWT =========
// PA=true : bands from P4 = (a,h,v,d) fp32; output OutT (fp16 a1r).
// PA=false: HV (half2), D (half), A (fp16 a1r); output fp32 (final).
template<int Hc, int Wc, int H, int W, int BB, int BLK, bool PA,
         int TM, int PR, int TWB, typename OutT>
__global__ void __launch_bounds__(BLK) idwt2_strip(
        const float4* __restrict__ P4,  const __half2* __restrict__ HV,
        const __half* __restrict__ Dp,  const __half* __restrict__ Ap,
        OutT* __restrict__ outd) {
    constexpr int RWH = PR + 3;                    // coeff rows per group
    constexpr int NG  = (TM / 2) / PR;             // groups
    constexpr int CC  = (TWB / 2 + 3 < Wc) ? TWB / 2 + 3 : Wc;  // logical coeff cols
    constexpr int CCP = (CC + 1) & ~1;             // even row stride for float2 LDS
    constexpr int NW  = BLK / 32;
    __shared__ __align__(16) float slo[TM][CCP];
    __shared__ __align__(16) float shi[TM][CCP];

    const int w0  = blockIdx.x * TWB;
    const int c0  = w0 >> 1;
    const int m0  = blockIdx.y * TM;
    const int nc  = blockIdx.z;
    const int tid = threadIdx.x;
    const float th = 0.3f * g_max[(BB + 0) * NC + nc];
    const float tv = 0.3f * g_max[(BB + 1) * NC + nc];
    const float td = 0.3f * g_max[(BB + 2) * NC + nc];

    // Phase A: NG*CC active threads; one independent vector-load batch each.
    if (tid < NG * CC) {
        const int g  = tid / CC;
        const int j  = tid - g * CC;
        const int pb = g * PR;
        const int qs = (m0 >> 1) + pb;
        const int cg = min(c0 + j, Wc - 1);        // clamped col feeds only masked outputs
        const size_t cb = (size_t)nc * Hc * Wc;

        float Aw[RWH], Hw[RWH], Vw[RWH], Dw[RWH];
        if constexpr (PA) {
            float4 Cw[RWH];
#pragma unroll
            for (int i = 0; i < RWH; i++) {
                int q = min(qs + i, Hc - 1);       // clamped rows feed only masked outputs
                Cw[i] = P4[cb + (unsigned)q * Wc + cg];
            }
#pragma unroll
            for (int i = 0; i < RWH; i++) {
                Aw[i] = Cw[i].x;
                Hw[i] = soft(Cw[i].y, th);
                Vw[i] = soft(Cw[i].z, tv);
                Dw[i] = soft(Cw[i].w, td);
            }
        } else {
            __half2 hv[RWH]; __half dv[RWH], av[RWH];
#pragma unroll
            for (int i = 0; i < RWH; i++) {
                int q = min(qs + i, Hc - 1);
                size_t o = cb + (unsigned)q * Wc + cg;
                hv[i] = HV[o];
                dv[i] = Dp[o];
                av[i] = Ap[o];
            }
#pragma unroll
            for (int i = 0; i < RWH; i++) {
                float2 f = __half22float2(hv[i]);
                Aw[i] = __half2float(av[i]);
                Hw[i] = soft(f.x, th);
                Vw[i] = soft(f.y, tv);
                Dw[i] = soft(__half2float(dv[i]), td);
            }
        }
#pragma unroll
        for (int pp = 0; pp < PR; pp++) {
            const int ml = 2 * (pb + pp);          // strip-local even output row
            float e_lo = 0.f, o_lo = 0.f, e_hi = 0.f, o_hi = 0.f;
#pragma unroll
            for (int i = 0; i < 4; i++) {
                e_lo = fmaf(Aw[pp + i], CLOf(6 - 2 * i), fmaf(Hw[pp + i], CHIf(6 - 2 * i), e_lo));
                o_lo = fmaf(Aw[pp + i], CLOf(7 - 2 * i), fmaf(Hw[pp + i], CHIf(7 - 2 * i), o_lo));
                e_hi = fmaf(Vw[pp + i], CLOf(6 - 2 * i), fmaf(Dw[pp + i], CHIf(6 - 2 * i), e_hi));
                o_hi = fmaf(Vw[pp + i], CLOf(7 - 2 * i), fmaf(Dw[pp + i], CHIf(7 - 2 * i), o_hi));
            }
            slo[ml][j]     = e_lo;
            slo[ml + 1][j] = o_lo;
            shi[ml][j]     = e_hi;
            shi[ml + 1][j] = o_hi;
        }
    }
    __syncthreads();

    // Phase B: row IDWT; 2 output pairs (4 pixels) per thread, vector stores.
    // (float4/uint2 widening rejected: W % 4 != 0 makes odd rows 8B-misaligned.)
    const int wid = tid >> 5, lane = tid & 31;
    const int we  = (w0 + TWB < W) ? w0 + TWB : W;
    const int NPb  = (we - w0) >> 1;               // output pairs (may be odd)
    const int NPPb = (NPb + 1) >> 1;
    for (int rr = wid; rr < TM; rr += NW) {
        int m = m0 + rr;
        if (m >= H) break;
        OutT* od = outd + (size_t)nc * H * W + (size_t)m * W + w0;
        for (int wp2 = lane; wp2 < NPPb; wp2 += 32) {
            const int wp = 2 * wp2;
            float2 l01 = *(const float2*)&slo[rr][wp];
            float2 l23 = *(const float2*)&slo[rr][wp + 2];
            float2 h01 = *(const float2*)&shi[rr][wp];
            float2 h23 = *(const float2*)&shi[rr][wp + 2];
            float ae0 = fmaf(l01.x, CLOf(6), fmaf(l01.y, CLOf(4), fmaf(l23.x, CLOf(2), fmaf(l23.y, CLOf(0),
                        fmaf(h01.x, CHIf(6), fmaf(h01.y, CHIf(4), fmaf(h23.x, CHIf(2), h23.y * CHIf(0))))))));
            float ao0 = fmaf(l01.x, CLOf(7), fmaf(l01.y, CLOf(5), fmaf(l23.x, CLOf(3), fmaf(l23.y, CLOf(1),
                        fmaf(h01.x, CHIf(7), fmaf(h01.y, CHIf(5), fmaf(h23.x, CHIf(3), h23.y * CHIf(1))))))));
            if constexpr (sizeof(OutT) == 2) {
                *(__half2*)&od[2 * wp] = __floats2half2_rn(ae0, ao0);
            } else {
                *(float2*)&od[2 * wp] = make_float2(ae0, ao0);
            }
            if (wp + 1 < NPb) {
                float l4 = (wp + 4 < CC) ? slo[rr][wp + 4] : 0.f;
                float h4 = (wp + 4 < CC) ? shi[rr][wp + 4] : 0.f;
                float ae1 = fmaf(l01.y, CLOf(6), fmaf(l23.x, CLOf(4), fmaf(l23.y, CLOf(2), fmaf(l4, CLOf(0),
                            fmaf(h01.y, CHIf(6), fmaf(h23.x, CHIf(4), fmaf(h23.y, CHIf(2), h4 * CHIf(0))))))));
                float ao1 = fmaf(l01.y, CLOf(7), fmaf(l23.x, CLOf(5), fmaf(l23.y, CLOf(3), fmaf(l4, CLOf(1),
                            fmaf(h01.y, CHIf(7), fmaf(h23.x, CHIf(5), fmaf(h23.y, CHIf(3), h4 * CHIf(1))))))));
                if constexpr (sizeof(OutT) == 2) {
                    *(__half2*)&od[2 * wp + 2] = __floats2half2_rn(ae1, ao1);
                } else {
                    *(float2*)&od[2 * wp + 2] = make_float2(ae1, ao1);
                }
            }
        }
    }
}

// ---------------- host ----------------
static inline unsigned cdiv(unsigned a, unsigned b) { return (a + b - 1) / b; }

extern "C" void kernel_launch(void* const* d_in, const int* in_sizes, int n_in,
                              void* d_out, int out_size) {
    (void)in_sizes; (void)n_in; (void)out_size;
    const float* x = (const float*)d_in[0];
    float* out = (float*)d_out;

    __half  *a1, *a1r, *d1;
    __half2 *hv1;
    float4  *p2;
    float   *gmax;
    cudaGetSymbolAddress((void**)&a1,   g_a1);
    cudaGetSymbolAddress((void**)&a1r,  g_a1r);
    cudaGetSymbolAddress((void**)&d1,   g_d1);
    cudaGetSymbolAddress((void**)&hv1,  g_hv1);
    cudaGetSymbolAddress((void**)&p2,   g_p2);
    cudaGetSymbolAddress((void**)&gmax, g_max);

    // Zero the band maxima via a captured memset node (replaces init_max kernel).
    cudaMemsetAsync(gmax, 0, 6 * NC * sizeof(float));

    // Level-1 analysis: x (fp32) -> a1/hv1/d1 (fp16).  PAIRED phase A, 256 thr.
    dwt2_strip<S0, S0, S1, S1, 0, 256, true, true, float>
        <<<dim3(cdiv(S1, 8), NC), 256>>>(x, a1, hv1, d1, nullptr);

    // Level-2 analysis: a1 (fp16) -> p2 (fp32).  Single-column phase A, 288 thr.
    dwt2_strip<S1, S1, S2, S2, 3, 288, false, false, __half>
        <<<dim3(cdiv(S2, 8), NC), 288>>>(a1, nullptr, nullptr, nullptr, p2);

    // Level-2 synthesis: p2 -> a1r (fp16).  TM=16, PR=4, no split.
    idwt2_strip<S2, S2, S1, S1, 3, 288, true, 16, 4, S1, __half>
        <<<dim3(1, cdiv(S1, 16), NC), 288>>>(p2, nullptr, nullptr, nullptr, a1r);

    // Level-1 synthesis: (a1r/hv1/d1 fp16) -> out (fp32).  TM=16, PR=4, split x2.
    idwt2_strip<S1, S1, S0, S0, 0, 288, false, 16, 4, 256, float>
        <<<dim3(2, cdiv(S0, 16), NC), 288>>>(nullptr, hv1, d1, a1r, out);
}